// round 1
// baseline (speedup 1.0000x reference)
#include <cuda_runtime.h>

#define B 32
#define S 4096
#define H 512
#define HC 16
#define RTILE 32

// Scratch (no allocations allowed in kernel_launch)
__device__ float g_dec_proj[B * H];
__device__ float g_pctx[8][B * H];

// ---------------------------------------------------------------------------
// Kernel 1: dec_proj[b,k] = decoder_hidden[b,:] @ W_dec[:,k] + b_dec[k]
// ---------------------------------------------------------------------------
__global__ void __launch_bounds__(H) k_decproj(const float* __restrict__ dh,
                                               const float* __restrict__ Wd,
                                               const float* __restrict__ bd) {
    __shared__ float s_dh[H];
    int b = blockIdx.x, k = threadIdx.x;
    s_dh[k] = dh[b * H + k];
    __syncthreads();
    float acc = bd[k];
#pragma unroll 8
    for (int h = 0; h < H; ++h) acc += s_dh[h] * Wd[h * H + k];
    g_dec_proj[b * H + k] = acc;
}

// ---------------------------------------------------------------------------
// Kernel 2: fused score = tanh(E @ W_enc + b_enc + dec_proj) @ W_v + b_v
// Block tile: 32 rows x 512 cols, 256 threads.
// Thread: 8 rows x 8 cols (4 f32x2 pairs) -> 32 FFMA2 per h.
// Uses sm_103a packed fma.rn.f32x2 for 2x fp32 FMA throughput.
// ---------------------------------------------------------------------------
__global__ void __launch_bounds__(256, 2) k_score(
    const float* __restrict__ E, const float* __restrict__ We,
    const float* __restrict__ be, const float* __restrict__ Wvv,
    const float* __restrict__ bv, float* __restrict__ scores) {
    __shared__ __align__(16) float sW[HC][H];       // 32 KB
    __shared__ __align__(8) float2 sE[RTILE][HC];   // 4 KB, value duplicated in .x/.y
    __shared__ float sDPB[H];
    __shared__ float sWv[H];
    __shared__ float sRed[4][2][8];

    int tid = threadIdx.x;
    int row0 = blockIdx.x * RTILE;      // 4096 % 32 == 0 -> one batch per block
    int b = row0 >> 12;

    for (int i = tid; i < H; i += 256) {
        sDPB[i] = g_dec_proj[b * H + i] + be[i];
        sWv[i] = Wvv[i];
    }

    int cgrp = tid & 63;   // 64 col groups (8 cols each, strided pairs)
    int rgrp = tid >> 6;   // 4 row groups (8 rows each); constant within a warp

    unsigned long long acc[8][4];
#pragma unroll
    for (int i = 0; i < 8; ++i)
#pragma unroll
        for (int j = 0; j < 4; ++j) acc[i][j] = 0ULL;

    const float* Eblk = E + (size_t)row0 * H;

    for (int h0 = 0; h0 < H; h0 += HC) {
        __syncthreads();
        // Load W tile: HC x 512 floats = 8192 -> 8 float4 per thread
        {
            const float4* wsrc = (const float4*)(We + (size_t)h0 * H);
            float4* wdst = (float4*)&sW[0][0];
#pragma unroll
            for (int q = 0; q < 8; ++q) wdst[tid + q * 256] = wsrc[tid + q * 256];
        }
        // Load E tile (32 x HC), duplicate each value into a float2 for LDS.64
#pragma unroll
        for (int q = 0; q < 2; ++q) {
            int e = tid + q * 256;
            int r = e >> 4, c = e & 15;
            float v = Eblk[(size_t)r * H + h0 + c];
            sE[r][c] = make_float2(v, v);
        }
        __syncthreads();

#pragma unroll
        for (int h = 0; h < HC; ++h) {
            unsigned long long ev[8], wp[4];
#pragma unroll
            for (int i = 0; i < 8; ++i)
                ev[i] = *(const unsigned long long*)&sE[rgrp * 8 + i][h];
#pragma unroll
            for (int j = 0; j < 4; ++j)
                wp[j] = *(const unsigned long long*)&sW[h][2 * cgrp + 128 * j];
#pragma unroll
            for (int i = 0; i < 8; ++i)
#pragma unroll
                for (int j = 0; j < 4; ++j)
                    asm("fma.rn.f32x2 %0, %1, %2, %0;"
                        : "+l"(acc[i][j]) : "l"(wp[j]), "l"(ev[i]));
        }
    }

    // Epilogue: tanh + dot with W_v, per-row partials
    float part[8];
#pragma unroll
    for (int i = 0; i < 8; ++i) {
        float p = 0.f;
#pragma unroll
        for (int j = 0; j < 4; ++j) {
            int c0 = 2 * (cgrp + 64 * j);
            float lo = __uint_as_float((unsigned)(acc[i][j] & 0xffffffffULL));
            float hi = __uint_as_float((unsigned)(acc[i][j] >> 32));
            p += tanhf(lo + sDPB[c0]) * sWv[c0];
            p += tanhf(hi + sDPB[c0 + 1]) * sWv[c0 + 1];
        }
        part[i] = p;
    }
    // Reduce across the 64 threads (2 warps) of this row group
#pragma unroll
    for (int i = 0; i < 8; ++i) {
#pragma unroll
        for (int off = 16; off; off >>= 1)
            part[i] += __shfl_xor_sync(0xffffffffu, part[i], off);
    }
    int wpair = (tid >> 5) & 1;
    if ((tid & 31) == 0) {
#pragma unroll
        for (int i = 0; i < 8; ++i) sRed[rgrp][wpair][i] = part[i];
    }
    __syncthreads();
    if (tid < RTILE) {
        int rg = tid >> 3, i = tid & 7;
        scores[row0 + rg * 8 + i] = sRed[rg][0][i] + sRed[rg][1][i] + bv[0];
    }
}

// ---------------------------------------------------------------------------
// Kernel 3: in-place softmax over S per batch
// ---------------------------------------------------------------------------
__global__ void __launch_bounds__(1024) k_softmax(float* __restrict__ w) {
    __shared__ float red[32];
    int b = blockIdx.x, tid = threadIdx.x;
    float* p = w + b * S;
    float v[4];
    float m = -1e30f;
#pragma unroll
    for (int i = 0; i < 4; ++i) { v[i] = p[tid + i * 1024]; m = fmaxf(m, v[i]); }
#pragma unroll
    for (int off = 16; off; off >>= 1) m = fmaxf(m, __shfl_xor_sync(~0u, m, off));
    if ((tid & 31) == 0) red[tid >> 5] = m;
    __syncthreads();
    if (tid < 32) {
        float t = red[tid];
#pragma unroll
        for (int off = 16; off; off >>= 1) t = fmaxf(t, __shfl_xor_sync(~0u, t, off));
        if (tid == 0) red[0] = t;
    }
    __syncthreads();
    m = red[0];
    __syncthreads();
    float s = 0.f;
#pragma unroll
    for (int i = 0; i < 4; ++i) { v[i] = expf(v[i] - m); s += v[i]; }
#pragma unroll
    for (int off = 16; off; off >>= 1) s += __shfl_xor_sync(~0u, s, off);
    if ((tid & 31) == 0) red[tid >> 5] = s;
    __syncthreads();
    if (tid < 32) {
        float t = red[tid];
#pragma unroll
        for (int off = 16; off; off >>= 1) t += __shfl_xor_sync(~0u, t, off);
        if (tid == 0) red[0] = t;
    }
    __syncthreads();
    float inv = 1.0f / red[0];
#pragma unroll
    for (int i = 0; i < 4; ++i) p[tid + i * 1024] = v[i] * inv;
}

// ---------------------------------------------------------------------------
// Kernel 4: context partials over S-chunks (deterministic, no atomics)
// grid (cc=4, sc=8, b=32), 128 threads; each thread one output column
// ---------------------------------------------------------------------------
__global__ void __launch_bounds__(128) k_ctx_partial(const float* __restrict__ E,
                                                     const float* __restrict__ w) {
    int b = blockIdx.z, sc = blockIdx.y, cc = blockIdx.x;
    int c = cc * 128 + threadIdx.x;
    const float* Eb = E + ((size_t)b * S + (size_t)sc * 512) * H + c;
    const float* wb = w + b * S + sc * 512;
    float a0 = 0.f, a1 = 0.f, a2 = 0.f, a3 = 0.f;
    for (int s = 0; s < 512; s += 4) {
        a0 += wb[s]     * Eb[(size_t)s * H];
        a1 += wb[s + 1] * Eb[(size_t)(s + 1) * H];
        a2 += wb[s + 2] * Eb[(size_t)(s + 2) * H];
        a3 += wb[s + 3] * Eb[(size_t)(s + 3) * H];
    }
    g_pctx[sc][b * H + c] = (a0 + a1) + (a2 + a3);
}

__global__ void __launch_bounds__(256) k_ctx_reduce(float* __restrict__ ctx) {
    int i = blockIdx.x * 256 + threadIdx.x;
    float a = 0.f;
#pragma unroll
    for (int k = 0; k < 8; ++k) a += g_pctx[k][i];
    ctx[i] = a;
}

// ---------------------------------------------------------------------------
extern "C" void kernel_launch(void* const* d_in, const int* in_sizes, int n_in,
                              void* d_out, int out_size) {
    const float* E  = (const float*)d_in[0];  // (B,S,H)
    const float* dh = (const float*)d_in[1];  // (B,H)
    const float* We = (const float*)d_in[2];  // (H,H)
    const float* be = (const float*)d_in[3];  // (H)
    const float* Wd = (const float*)d_in[4];  // (H,H)
    const float* bd = (const float*)d_in[5];  // (H)
    const float* Wv = (const float*)d_in[6];  // (H,1)
    const float* bv = (const float*)d_in[7];  // (1)
    float* out = (float*)d_out;
    float* ctx = out;             // (B,H)  = 16384 floats
    float* wts = out + B * H;     // (B,S)  = 131072 floats

    k_decproj<<<B, H>>>(dh, Wd, bd);
    k_score<<<(B * S) / RTILE, 256>>>(E, We, be, Wv, bv, wts);
    k_softmax<<<B, 1024>>>(wts);
    k_ctx_partial<<<dim3(4, 8, B), 128>>>(E, wts);
    k_ctx_reduce<<<(B * H) / 256, 256>>>(ctx);
}

// round 3
// speedup vs baseline: 1.7508x; 1.7508x over previous
#include <cuda_runtime.h>
#include <cuda_bf16.h>
#include <cstdint>

#define B 32
#define S 4096
#define H 512

// ---------------- scratch (no allocs allowed) ----------------
__device__ float g_dec_proj[B * H];
__device__ float g_pctx[16][B * H];
__device__ __align__(16) __nv_bfloat16 g_Wh[H * H];   // W_enc^T hi, [n][k]
__device__ __align__(16) __nv_bfloat16 g_Wl[H * H];   // W_enc^T lo
__device__ __align__(16) __nv_bfloat16 g_Eh[B * S * H];  // E hi (256 MB)
__device__ __align__(16) __nv_bfloat16 g_El[B * S * H];  // E lo (256 MB)

// ---------------- helpers ----------------
__device__ __forceinline__ uint32_t smem_u32(const void* p) {
    uint32_t a;
    asm("{ .reg .u64 t; cvta.to.shared.u64 t, %1; cvt.u32.u64 %0, t; }" : "=r"(a) : "l"(p));
    return a;
}
// accurate-enough fast tanh: 1 - 2/(exp(2x)+1) via MUFU ex2/rcp (abs err ~1e-7)
__device__ __forceinline__ float tanh_fast(float x) {
    float e, r;
    asm("ex2.approx.f32 %0, %1;" : "=f"(e) : "f"(x * 2.8853900817779268f));
    asm("rcp.approx.f32 %0, %1;" : "=f"(r) : "f"(e + 1.0f));
    return 1.0f - 2.0f * r;
}
__device__ __forceinline__ void cp16(uint32_t dst, const void* src) {
    asm volatile("cp.async.ca.shared.global [%0], [%1], 16;" :: "r"(dst), "l"(src));
}
__device__ __forceinline__ void ldsm4(uint32_t* r, uint32_t a) {
    asm volatile("ldmatrix.sync.aligned.m8n8.x4.shared.b16 {%0,%1,%2,%3}, [%4];"
                 : "=r"(r[0]), "=r"(r[1]), "=r"(r[2]), "=r"(r[3]) : "r"(a));
}
__device__ __forceinline__ void mma16816(float* d, const uint32_t* a,
                                         uint32_t b0, uint32_t b1) {
    asm volatile(
        "mma.sync.aligned.m16n8k16.row.col.f32.bf16.bf16.f32 "
        "{%0,%1,%2,%3}, {%4,%5,%6,%7}, {%8,%9}, {%0,%1,%2,%3};"
        : "+f"(d[0]), "+f"(d[1]), "+f"(d[2]), "+f"(d[3])
        : "r"(a[0]), "r"(a[1]), "r"(a[2]), "r"(a[3]), "r"(b0), "r"(b1));
}

// ---------------- SMEM layout (dynamic) for k_score ----------------
#define SA   0        // A: 2 parts x 64 rows x 512 k bf16 = 131072 B
#define SB   131072   // B: 2 bufs x (2 parts x 128 n x 64 k bf16) = 65536 B
#define SDPB 196608   // 512 f32
#define SWV  198656   // 512 f32
#define SRED 200704   // 2 x 64 f32
#define SMEM_SZ 201216

// ---------------------------------------------------------------------------
// Kernel 0a: split-transpose W_enc -> g_Wh/g_Wl  ([n][k], k-contiguous)
// ---------------------------------------------------------------------------
__global__ void __launch_bounds__(256) k_wconv(const float* __restrict__ W) {
    __shared__ float t[32][33];
    int tx = threadIdx.x & 31, ty = threadIdx.x >> 5;
    int k0 = blockIdx.x * 32, h0 = blockIdx.y * 32;
#pragma unroll
    for (int q = 0; q < 4; ++q)
        t[ty + q * 8][tx] = W[(size_t)(h0 + ty + q * 8) * H + k0 + tx];
    __syncthreads();
#pragma unroll
    for (int q = 0; q < 4; ++q) {
        float v = t[tx][ty + q * 8];
        __nv_bfloat16 hi = __float2bfloat16(v);
        __nv_bfloat16 lo = __float2bfloat16(v - __bfloat162float(hi));
        size_t o = (size_t)(k0 + ty + q * 8) * H + h0 + tx;
        g_Wh[o] = hi;
        g_Wl[o] = lo;
    }
}

// ---------------------------------------------------------------------------
// Kernel 0b: split E -> g_Eh/g_El (bf16 hi/lo)
// ---------------------------------------------------------------------------
__global__ void __launch_bounds__(256) k_esplit(const float* __restrict__ E) {
    size_t i = (size_t)blockIdx.x * 256 + threadIdx.x;   // float4 index
    float4 v = ((const float4*)E)[i];
    __nv_bfloat16 hx = __float2bfloat16(v.x), hy = __float2bfloat16(v.y);
    __nv_bfloat16 hz = __float2bfloat16(v.z), hw = __float2bfloat16(v.w);
    __nv_bfloat162 h01(hx, hy), h23(hz, hw);
    __nv_bfloat162 l01(__float2bfloat16(v.x - __bfloat162float(hx)),
                       __float2bfloat16(v.y - __bfloat162float(hy)));
    __nv_bfloat162 l23(__float2bfloat16(v.z - __bfloat162float(hz)),
                       __float2bfloat16(v.w - __bfloat162float(hw)));
    ((uint2*)g_Eh)[i] = make_uint2(*(uint32_t*)&h01, *(uint32_t*)&h23);
    ((uint2*)g_El)[i] = make_uint2(*(uint32_t*)&l01, *(uint32_t*)&l23);
}

// ---------------------------------------------------------------------------
// Kernel 1: dec_proj
// ---------------------------------------------------------------------------
__global__ void __launch_bounds__(H) k_decproj(const float* __restrict__ dh,
                                               const float* __restrict__ Wd,
                                               const float* __restrict__ bd) {
    __shared__ float s_dh[H];
    int b = blockIdx.x, k = threadIdx.x;
    s_dh[k] = dh[b * H + k];
    __syncthreads();
    float acc = bd[k];
#pragma unroll 8
    for (int h = 0; h < H; ++h) acc += s_dh[h] * Wd[h * H + k];
    g_dec_proj[b * H + k] = acc;
}

// ---------------------------------------------------------------------------
// Kernel 2: HMMA (mma.sync bf16 3-split) fused score kernel.
// CTA: M=64 rows, all N=512 (4 chunks of 128), K=512 in 8 chunks of 64.
// A (hi/lo, full K) resident in SMEM; B double-buffered via cp.async.
// ---------------------------------------------------------------------------
__global__ void __launch_bounds__(256, 1) k_score(
    const float* __restrict__ be, const float* __restrict__ Wvv,
    const float* __restrict__ bv, float* __restrict__ scores) {
    extern __shared__ char smem[];
    uint32_t sb = smem_u32(smem);
    int tid = threadIdx.x;
    int lane = tid & 31, w = tid >> 5;
    int m0blk = blockIdx.x * 64;
    int b = m0blk >> 12;

    float* sDPB = (float*)(smem + SDPB);
    float* sWv  = (float*)(smem + SWV);
    float* sRed = (float*)(smem + SRED);
    for (int i = tid; i < H; i += 256) {
        sDPB[i] = g_dec_proj[b * H + i] + be[i];
        sWv[i]  = Wvv[i];
    }

    // ---- prologue: A (both parts, full K) + B chunk 0 via cp.async ----
#pragma unroll
    for (int q = 0; q < 32; ++q) {
        int t = tid + q * 256;                    // 0..8191 16B-chunks
        int part = t >> 12, r = (t >> 6) & 63, c = t & 63;
        const __nv_bfloat16* src = (part ? g_El : g_Eh) + (size_t)(m0blk + r) * H + c * 8;
        cp16(sb + SA + part * 65536 + r * 1024 + (((uint32_t)(c ^ (r & 7))) << 4), src);
    }
#pragma unroll
    for (int q = 0; q < 8; ++q) {
        int t = tid + q * 256;                    // 0..2047
        int part = t >> 10, r = (t >> 3) & 127, c = t & 7;
        const __nv_bfloat16* src = (part ? g_Wl : g_Wh) + (size_t)r * H + c * 8;
        cp16(sb + SB + part * 16384 + r * 128 + (((uint32_t)(c ^ (r & 7))) << 4), src);
    }
    asm volatile("cp.async.commit_group;" ::: "memory");

    int m0w = (w & 3) * 16;       // warp m offset in tile
    int nh = (w >> 2) * 64;       // warp n offset within 128-chunk

    float acc[8][4];
#pragma unroll
    for (int f = 0; f < 8; ++f)
#pragma unroll
        for (int j = 0; j < 4; ++j) acc[f][j] = 0.f;
    float p0 = 0.f, p1 = 0.f;

    int mat = lane >> 3, rl = lane & 7;

    for (int s = 0; s < 32; ++s) {
        int buf = s & 1;
        // issue loads for chunk s+1 into the other buffer
        if (s < 31) {
            int s1 = s + 1;
            int nc1 = s1 >> 3, kc1 = s1 & 7, buf1 = s1 & 1;
#pragma unroll
            for (int q = 0; q < 8; ++q) {
                int t = tid + q * 256;
                int part = t >> 10, r = (t >> 3) & 127, c = t & 7;
                const __nv_bfloat16* src = (part ? g_Wl : g_Wh) +
                    (size_t)(nc1 * 128 + r) * H + kc1 * 64 + c * 8;
                cp16(sb + SB + buf1 * 32768 + part * 16384 + r * 128 +
                     (((uint32_t)(c ^ (r & 7))) << 4), src);
            }
            asm volatile("cp.async.commit_group;" ::: "memory");
            asm volatile("cp.async.wait_group 1;" ::: "memory");
        } else {
            asm volatile("cp.async.wait_group 0;" ::: "memory");
        }
        __syncthreads();

        int kc = s & 7;
        uint32_t bbase = sb + SB + buf * 32768;
#pragma unroll
        for (int kk = 0; kk < 4; ++kk) {
            // A fragments hi/lo: m16 x k16
            uint32_t ah[4], al[4];
            {
                int row = m0w + (mat & 1) * 8 + rl;
                int ch = kc * 8 + kk * 2 + (mat >> 1);
                uint32_t off = (uint32_t)(row * 1024 + ((ch ^ (row & 7)) << 4));
                ldsm4(ah, sb + SA + off);
                ldsm4(al, sb + SA + 65536 + off);
            }
            // B fragments hi/lo: 4 groups of n16 x k16
            uint32_t bh[4][4], bl[4][4];
#pragma unroll
            for (int nf = 0; nf < 4; ++nf) {
                int row = nh + nf * 16 + (mat & 1) * 8 + rl;
                int ch = kk * 2 + (mat >> 1);
                uint32_t off = (uint32_t)(row * 128 + ((ch ^ (row & 7)) << 4));
                ldsm4(bh[nf], bbase + off);
                ldsm4(bl[nf], bbase + 16384 + off);
            }
            // 24 MMAs: hh, lh, hl
#pragma unroll
            for (int nf = 0; nf < 4; ++nf) {
                mma16816(acc[nf * 2],     ah, bh[nf][0], bh[nf][2]);
                mma16816(acc[nf * 2 + 1], ah, bh[nf][1], bh[nf][3]);
            }
#pragma unroll
            for (int nf = 0; nf < 4; ++nf) {
                mma16816(acc[nf * 2],     al, bh[nf][0], bh[nf][2]);
                mma16816(acc[nf * 2 + 1], al, bh[nf][1], bh[nf][3]);
            }
#pragma unroll
            for (int nf = 0; nf < 4; ++nf) {
                mma16816(acc[nf * 2],     ah, bl[nf][0], bl[nf][2]);
                mma16816(acc[nf * 2 + 1], ah, bl[nf][1], bl[nf][3]);
            }
        }

        // end of an N-chunk: fold accumulators into score partials
        if (kc == 7) {
            int nc = s >> 3;
#pragma unroll
            for (int f = 0; f < 8; ++f) {
                int c0 = nc * 128 + nh + f * 8 + (lane & 3) * 2;
                p0 += tanh_fast(acc[f][0] + sDPB[c0]) * sWv[c0]
                    + tanh_fast(acc[f][1] + sDPB[c0 + 1]) * sWv[c0 + 1];
                p1 += tanh_fast(acc[f][2] + sDPB[c0]) * sWv[c0]
                    + tanh_fast(acc[f][3] + sDPB[c0 + 1]) * sWv[c0 + 1];
#pragma unroll
                for (int j = 0; j < 4; ++j) acc[f][j] = 0.f;
            }
        }
        __syncthreads();
    }

    // reduce over the 4 lanes (lane&3) holding different columns
    p0 += __shfl_xor_sync(~0u, p0, 1); p0 += __shfl_xor_sync(~0u, p0, 2);
    p1 += __shfl_xor_sync(~0u, p1, 1); p1 += __shfl_xor_sync(~0u, p1, 2);
    if ((lane & 3) == 0) {
        int gid = lane >> 2;
        sRed[(w >> 2) * 64 + m0w + gid] = p0;
        sRed[(w >> 2) * 64 + m0w + 8 + gid] = p1;
    }
    __syncthreads();
    if (tid < 64)
        scores[m0blk + tid] = sRed[tid] + sRed[64 + tid] + __ldg(bv);
}

// ---------------------------------------------------------------------------
// Kernel 3: in-place softmax over S per batch
// ---------------------------------------------------------------------------
__global__ void __launch_bounds__(1024) k_softmax(float* __restrict__ w) {
    __shared__ float red[32];
    int b = blockIdx.x, tid = threadIdx.x;
    float* p = w + b * S;
    float v[4];
    float m = -1e30f;
#pragma unroll
    for (int i = 0; i < 4; ++i) { v[i] = p[tid + i * 1024]; m = fmaxf(m, v[i]); }
#pragma unroll
    for (int off = 16; off; off >>= 1) m = fmaxf(m, __shfl_xor_sync(~0u, m, off));
    if ((tid & 31) == 0) red[tid >> 5] = m;
    __syncthreads();
    if (tid < 32) {
        float t = red[tid];
#pragma unroll
        for (int off = 16; off; off >>= 1) t = fmaxf(t, __shfl_xor_sync(~0u, t, off));
        if (tid == 0) red[0] = t;
    }
    __syncthreads();
    m = red[0];
    __syncthreads();
    float s = 0.f;
#pragma unroll
    for (int i = 0; i < 4; ++i) { v[i] = expf(v[i] - m); s += v[i]; }
#pragma unroll
    for (int off = 16; off; off >>= 1) s += __shfl_xor_sync(~0u, s, off);
    if ((tid & 31) == 0) red[tid >> 5] = s;
    __syncthreads();
    if (tid < 32) {
        float t = red[tid];
#pragma unroll
        for (int off = 16; off; off >>= 1) t += __shfl_xor_sync(~0u, t, off);
        if (tid == 0) red[0] = t;
    }
    __syncthreads();
    float inv = 1.0f / red[0];
#pragma unroll
    for (int i = 0; i < 4; ++i) p[tid + i * 1024] = v[i] * inv;
}

// ---------------------------------------------------------------------------
// Kernel 4: context partials (float4 columns)
// ---------------------------------------------------------------------------
__global__ void __launch_bounds__(128) k_ctx_partial(const float* __restrict__ E,
                                                     const float* __restrict__ w) {
    int b = blockIdx.y, sc = blockIdx.x;
    const float4* Eb = (const float4*)(E + ((size_t)b * S + (size_t)sc * 256) * H) + threadIdx.x;
    const float* wb = w + b * S + sc * 256;
    float4 acc = make_float4(0.f, 0.f, 0.f, 0.f);
#pragma unroll 4
    for (int s = 0; s < 256; ++s) {
        float ws = __ldg(wb + s);
        float4 e = Eb[(size_t)s * 128];
        acc.x += ws * e.x; acc.y += ws * e.y; acc.z += ws * e.z; acc.w += ws * e.w;
    }
    ((float4*)&g_pctx[sc][b * H])[threadIdx.x] = acc;
}

__global__ void __launch_bounds__(256) k_ctx_reduce(float* __restrict__ ctx) {
    int i = blockIdx.x * 256 + threadIdx.x;
    float a = 0.f;
#pragma unroll
    for (int k = 0; k < 16; ++k) a += g_pctx[k][i];
    ctx[i] = a;
}

// ---------------------------------------------------------------------------
extern "C" void kernel_launch(void* const* d_in, const int* in_sizes, int n_in,
                              void* d_out, int out_size) {
    const float* E  = (const float*)d_in[0];
    const float* dh = (const float*)d_in[1];
    const float* We = (const float*)d_in[2];
    const float* be = (const float*)d_in[3];
    const float* Wd = (const float*)d_in[4];
    const float* bd = (const float*)d_in[5];
    const float* Wv = (const float*)d_in[6];
    const float* bv = (const float*)d_in[7];
    float* out = (float*)d_out;
    float* ctx = out;
    float* wts = out + B * H;

    cudaFuncSetAttribute(k_score, cudaFuncAttributeMaxDynamicSharedMemorySize, SMEM_SZ);

    k_wconv<<<dim3(16, 16), 256>>>(We);
    k_esplit<<<(B * S * H) / (4 * 256), 256>>>(E);
    k_decproj<<<B, H>>>(dh, Wd, bd);
    k_score<<<(B * S) / 64, 256, SMEM_SZ>>>(be, Wv, bv, wts);
    k_softmax<<<B, 1024>>>(wts);
    k_ctx_partial<<<dim3(16, B), 128>>>(E, wts);
    k_ctx_reduce<<<(B * H) / 256, 256>>>(ctx);
}

// round 4
// speedup vs baseline: 1.9666x; 1.1232x over previous
#include <cuda_runtime.h>
#include <cuda_bf16.h>
#include <cstdint>

#define B 32
#define S 4096
#define H 512

// ---------------- scratch (no allocs allowed) ----------------
__device__ float g_dec_proj[B * H];
__device__ float g_pctx[16][B * H];
__device__ __align__(16) __nv_bfloat16 g_Wh[H * H];      // W_enc^T hi, [n][k]
__device__ __align__(16) __nv_bfloat16 g_Wl[H * H];      // W_enc^T lo
__device__ __align__(16) __nv_bfloat16 g_Eh[B * S * H];  // E hi
__device__ __align__(16) __nv_bfloat16 g_El[B * S * H];  // E lo

// ---------------- helpers ----------------
__device__ __forceinline__ uint32_t smem_u32(const void* p) {
    uint32_t a;
    asm("{ .reg .u64 t; cvta.to.shared.u64 t, %1; cvt.u32.u64 %0, t; }" : "=r"(a) : "l"(p));
    return a;
}
// fast tanh: 1 - 2/(exp2(2x/ln2)+1) via MUFU (abs err ~1e-7)
__device__ __forceinline__ float tanh_fast(float x) {
    float e, r;
    asm("ex2.approx.f32 %0, %1;" : "=f"(e) : "f"(x * 2.8853900817779268f));
    asm("rcp.approx.f32 %0, %1;" : "=f"(r) : "f"(e + 1.0f));
    return 1.0f - 2.0f * r;
}
__device__ __forceinline__ void cp16(uint32_t dst, const void* src) {
    asm volatile("cp.async.ca.shared.global [%0], [%1], 16;" :: "r"(dst), "l"(src));
}
__device__ __forceinline__ void ldsm4(uint32_t* r, uint32_t a) {
    asm volatile("ldmatrix.sync.aligned.m8n8.x4.shared.b16 {%0,%1,%2,%3}, [%4];"
                 : "=r"(r[0]), "=r"(r[1]), "=r"(r[2]), "=r"(r[3]) : "r"(a));
}
__device__ __forceinline__ void mma16816(float* d, const uint32_t* a,
                                         uint32_t b0, uint32_t b1) {
    asm volatile(
        "mma.sync.aligned.m16n8k16.row.col.f32.bf16.bf16.f32 "
        "{%0,%1,%2,%3}, {%4,%5,%6,%7}, {%8,%9}, {%0,%1,%2,%3};"
        : "+f"(d[0]), "+f"(d[1]), "+f"(d[2]), "+f"(d[3])
        : "r"(a[0]), "r"(a[1]), "r"(a[2]), "r"(a[3]), "r"(b0), "r"(b1));
}

// ---------------- SMEM layout for k_score ----------------
// 3 stages x 32KB: per stage [Ah 8K][Al 8K][Bh 8K][Bl 8K]
#define ST_SZ 32768
#define SDPB  98304
#define SWV   100352
#define SRED  102400
#define SMEM_SZ 104448

// ---------------------------------------------------------------------------
// Kernel 0a: split-transpose W_enc -> g_Wh/g_Wl  ([n][k], k-contiguous)
// ---------------------------------------------------------------------------
__global__ void __launch_bounds__(256) k_wconv(const float* __restrict__ W) {
    __shared__ float t[32][33];
    int tx = threadIdx.x & 31, ty = threadIdx.x >> 5;
    int k0 = blockIdx.x * 32, h0 = blockIdx.y * 32;
#pragma unroll
    for (int q = 0; q < 4; ++q)
        t[ty + q * 8][tx] = W[(size_t)(h0 + ty + q * 8) * H + k0 + tx];
    __syncthreads();
#pragma unroll
    for (int q = 0; q < 4; ++q) {
        float v = t[tx][ty + q * 8];
        __nv_bfloat16 hi = __float2bfloat16(v);
        __nv_bfloat16 lo = __float2bfloat16(v - __bfloat162float(hi));
        size_t o = (size_t)(k0 + ty + q * 8) * H + h0 + tx;
        g_Wh[o] = hi;
        g_Wl[o] = lo;
    }
}

// ---------------------------------------------------------------------------
// Kernel 0b: split E -> g_Eh/g_El (bf16 hi/lo)
// ---------------------------------------------------------------------------
__global__ void __launch_bounds__(256) k_esplit(const float* __restrict__ E) {
    size_t i = (size_t)blockIdx.x * 256 + threadIdx.x;
    float4 v = ((const float4*)E)[i];
    __nv_bfloat16 hx = __float2bfloat16(v.x), hy = __float2bfloat16(v.y);
    __nv_bfloat16 hz = __float2bfloat16(v.z), hw = __float2bfloat16(v.w);
    __nv_bfloat162 h01(hx, hy), h23(hz, hw);
    __nv_bfloat162 l01(__float2bfloat16(v.x - __bfloat162float(hx)),
                       __float2bfloat16(v.y - __bfloat162float(hy)));
    __nv_bfloat162 l23(__float2bfloat16(v.z - __bfloat162float(hz)),
                       __float2bfloat16(v.w - __bfloat162float(hw)));
    ((uint2*)g_Eh)[i] = make_uint2(*(uint32_t*)&h01, *(uint32_t*)&h23);
    ((uint2*)g_El)[i] = make_uint2(*(uint32_t*)&l01, *(uint32_t*)&l23);
}

// ---------------------------------------------------------------------------
// Kernel 1: dec_proj
// ---------------------------------------------------------------------------
__global__ void __launch_bounds__(H) k_decproj(const float* __restrict__ dh,
                                               const float* __restrict__ Wd,
                                               const float* __restrict__ bd) {
    __shared__ float s_dh[H];
    int b = blockIdx.x, k = threadIdx.x;
    s_dh[k] = dh[b * H + k];
    __syncthreads();
    float acc = bd[k];
#pragma unroll 8
    for (int h = 0; h < H; ++h) acc += s_dh[h] * Wd[h * H + k];
    g_dec_proj[b * H + k] = acc;
}

// ---------------------------------------------------------------------------
// Kernel 2: HMMA fused score. 512 threads, 16 warps (4m x 4n), warp m32 x n32.
// CTA M=128, N in 4 chunks of 128, K in 16 chunks of 32.
// A and B both streamed as K32 tiles via 3-stage cp.async ring.
// ---------------------------------------------------------------------------
__device__ __forceinline__ void score_issue(uint32_t sb, int s, int m0blk, int tid) {
    int nc = s >> 4, kc = s & 15, st = s % 3;
    uint32_t dbase = sb + st * ST_SZ;
#pragma unroll
    for (int q = 0; q < 4; ++q) {
        int idx = tid + q * 512;              // 0..2047
        int tile = idx >> 10;                 // 0=A, 1=B
        int part = (idx >> 9) & 1;            // 0=hi, 1=lo
        int r = (idx >> 2) & 127;
        int c = idx & 3;
        const __nv_bfloat16* src;
        if (tile == 0)
            src = (part ? g_El : g_Eh) + (size_t)(m0blk + r) * H + kc * 32 + c * 8;
        else
            src = (part ? g_Wl : g_Wh) + (size_t)(nc * 128 + r) * H + kc * 32 + c * 8;
        uint32_t dst = dbase + tile * 16384 + part * 8192 + r * 64 +
                       (((uint32_t)(c ^ ((r >> 1) & 3))) << 4);
        cp16(dst, src);
    }
    asm volatile("cp.async.commit_group;" ::: "memory");
}

__global__ void __launch_bounds__(512, 1) k_score(
    const float* __restrict__ be, const float* __restrict__ Wvv,
    const float* __restrict__ bv, float* __restrict__ scores) {
    extern __shared__ char smem[];
    uint32_t sb = smem_u32(smem);
    int tid = threadIdx.x;
    int lane = tid & 31, w = tid >> 5;
    int wm = w & 3, wn = w >> 2;
    int m0blk = blockIdx.x * 128;
    int b = m0blk >> 12;

    float* sDPB = (float*)(smem + SDPB);
    float* sWv  = (float*)(smem + SWV);
    float* sRed = (float*)(smem + SRED);   // [4][128]
    if (tid < H) {
        sDPB[tid] = g_dec_proj[b * H + tid] + be[tid];
        sWv[tid]  = Wvv[tid];
    }

    score_issue(sb, 0, m0blk, tid);
    score_issue(sb, 1, m0blk, tid);

    int mat = lane >> 3, rl = lane & 7;
    float acc[2][4][4];
#pragma unroll
    for (int mi = 0; mi < 2; ++mi)
#pragma unroll
        for (int nj = 0; nj < 4; ++nj)
#pragma unroll
            for (int q = 0; q < 4; ++q) acc[mi][nj][q] = 0.f;
    float p[4] = {0.f, 0.f, 0.f, 0.f};

#pragma unroll 1
    for (int s = 0; s < 64; ++s) {
        if (s < 63) { asm volatile("cp.async.wait_group 1;" ::: "memory"); }
        else        { asm volatile("cp.async.wait_group 0;" ::: "memory"); }
        __syncthreads();
        if (s + 2 < 64) score_issue(sb, s + 2, m0blk, tid);

        int nc = s >> 4, kc = s & 15, st = s % 3;
        uint32_t abase = sb + st * ST_SZ;
        uint32_t bbase = abase + 16384;

#pragma unroll
        for (int kk = 0; kk < 2; ++kk) {
            int ch = kk * 2 + (mat >> 1);
            uint32_t ah[2][4], al[2][4], bh[2][4], bl[2][4];
#pragma unroll
            for (int mi = 0; mi < 2; ++mi) {
                int row = wm * 32 + mi * 16 + (mat & 1) * 8 + rl;
                uint32_t off = (uint32_t)(row * 64 + ((ch ^ ((row >> 1) & 3)) << 4));
                ldsm4(ah[mi], abase + off);
                ldsm4(al[mi], abase + 8192 + off);
            }
#pragma unroll
            for (int nt = 0; nt < 2; ++nt) {
                int row = wn * 32 + nt * 16 + (mat & 1) * 8 + rl;
                uint32_t off = (uint32_t)(row * 64 + ((ch ^ ((row >> 1) & 3)) << 4));
                ldsm4(bh[nt], bbase + off);
                ldsm4(bl[nt], bbase + 8192 + off);
            }
#pragma unroll
            for (int mi = 0; mi < 2; ++mi)
#pragma unroll
                for (int nt = 0; nt < 2; ++nt) {
                    mma16816(acc[mi][nt * 2],     ah[mi], bh[nt][0], bh[nt][2]);
                    mma16816(acc[mi][nt * 2 + 1], ah[mi], bh[nt][1], bh[nt][3]);
                    mma16816(acc[mi][nt * 2],     al[mi], bh[nt][0], bh[nt][2]);
                    mma16816(acc[mi][nt * 2 + 1], al[mi], bh[nt][1], bh[nt][3]);
                    mma16816(acc[mi][nt * 2],     ah[mi], bl[nt][0], bl[nt][2]);
                    mma16816(acc[mi][nt * 2 + 1], ah[mi], bl[nt][1], bl[nt][3]);
                }
        }

        if (kc == 15) {   // end of N-chunk: fold into score partials
#pragma unroll
            for (int mi = 0; mi < 2; ++mi)
#pragma unroll
                for (int nj = 0; nj < 4; ++nj) {
                    int c0 = nc * 128 + wn * 32 + nj * 8 + (lane & 3) * 2;
                    float d0 = sDPB[c0], d1 = sDPB[c0 + 1];
                    float v0 = sWv[c0],  v1 = sWv[c0 + 1];
                    p[mi * 2]     += tanh_fast(acc[mi][nj][0] + d0) * v0
                                   + tanh_fast(acc[mi][nj][1] + d1) * v1;
                    p[mi * 2 + 1] += tanh_fast(acc[mi][nj][2] + d0) * v0
                                   + tanh_fast(acc[mi][nj][3] + d1) * v1;
#pragma unroll
                    for (int q = 0; q < 4; ++q) acc[mi][nj][q] = 0.f;
                }
        }
    }

    // reduce over lane&3 (4 col groups)
#pragma unroll
    for (int i = 0; i < 4; ++i) {
        p[i] += __shfl_xor_sync(~0u, p[i], 1);
        p[i] += __shfl_xor_sync(~0u, p[i], 2);
    }
    if ((lane & 3) == 0) {
        int g = lane >> 2;
        sRed[wn * 128 + wm * 32 + g]      = p[0];
        sRed[wn * 128 + wm * 32 + 8 + g]  = p[1];
        sRed[wn * 128 + wm * 32 + 16 + g] = p[2];
        sRed[wn * 128 + wm * 32 + 24 + g] = p[3];
    }
    __syncthreads();
    if (tid < 128) {
        scores[m0blk + tid] = sRed[tid] + sRed[128 + tid] + sRed[256 + tid] +
                              sRed[384 + tid] + __ldg(bv);
    }
}

// ---------------------------------------------------------------------------
// Kernel 3: in-place softmax over S per batch
// ---------------------------------------------------------------------------
__global__ void __launch_bounds__(1024) k_softmax(float* __restrict__ w) {
    __shared__ float red[32];
    int b = blockIdx.x, tid = threadIdx.x;
    float* p = w + b * S;
    float v[4];
    float m = -1e30f;
#pragma unroll
    for (int i = 0; i < 4; ++i) { v[i] = p[tid + i * 1024]; m = fmaxf(m, v[i]); }
#pragma unroll
    for (int off = 16; off; off >>= 1) m = fmaxf(m, __shfl_xor_sync(~0u, m, off));
    if ((tid & 31) == 0) red[tid >> 5] = m;
    __syncthreads();
    if (tid < 32) {
        float t = red[tid];
#pragma unroll
        for (int off = 16; off; off >>= 1) t = fmaxf(t, __shfl_xor_sync(~0u, t, off));
        if (tid == 0) red[0] = t;
    }
    __syncthreads();
    m = red[0];
    __syncthreads();
    float s = 0.f;
#pragma unroll
    for (int i = 0; i < 4; ++i) { v[i] = expf(v[i] - m); s += v[i]; }
#pragma unroll
    for (int off = 16; off; off >>= 1) s += __shfl_xor_sync(~0u, s, off);
    if ((tid & 31) == 0) red[tid >> 5] = s;
    __syncthreads();
    if (tid < 32) {
        float t = red[tid];
#pragma unroll
        for (int off = 16; off; off >>= 1) t += __shfl_xor_sync(~0u, t, off);
        if (tid == 0) red[0] = t;
    }
    __syncthreads();
    float inv = 1.0f / red[0];
#pragma unroll
    for (int i = 0; i < 4; ++i) p[tid + i * 1024] = v[i] * inv;
}

// ---------------------------------------------------------------------------
// Kernel 4: context partials (float4 columns)
// ---------------------------------------------------------------------------
__global__ void __launch_bounds__(128) k_ctx_partial(const float* __restrict__ E,
                                                     const float* __restrict__ w) {
    int b = blockIdx.y, sc = blockIdx.x;
    const float4* Eb = (const float4*)(E + ((size_t)b * S + (size_t)sc * 256) * H) + threadIdx.x;
    const float* wb = w + b * S + sc * 256;
    float4 acc = make_float4(0.f, 0.f, 0.f, 0.f);
#pragma unroll 4
    for (int s = 0; s < 256; ++s) {
        float ws = __ldg(wb + s);
        float4 e = Eb[(size_t)s * 128];
        acc.x += ws * e.x; acc.y += ws * e.y; acc.z += ws * e.z; acc.w += ws * e.w;
    }
    ((float4*)&g_pctx[sc][b * H])[threadIdx.x] = acc;
}

__global__ void __launch_bounds__(256) k_ctx_reduce(float* __restrict__ ctx) {
    int i = blockIdx.x * 256 + threadIdx.x;
    float a = 0.f;
#pragma unroll
    for (int k = 0; k < 16; ++k) a += g_pctx[k][i];
    ctx[i] = a;
}

// ---------------------------------------------------------------------------
extern "C" void kernel_launch(void* const* d_in, const int* in_sizes, int n_in,
                              void* d_out, int out_size) {
    const float* E  = (const float*)d_in[0];
    const float* dh = (const float*)d_in[1];
    const float* We = (const float*)d_in[2];
    const float* be = (const float*)d_in[3];
    const float* Wd = (const float*)d_in[4];
    const float* bd = (const float*)d_in[5];
    const float* Wv = (const float*)d_in[6];
    const float* bv = (const float*)d_in[7];
    float* out = (float*)d_out;
    float* ctx = out;
    float* wts = out + B * H;

    cudaFuncSetAttribute(k_score, cudaFuncAttributeMaxDynamicSharedMemorySize, SMEM_SZ);

    k_wconv<<<dim3(16, 16), 256>>>(We);
    k_esplit<<<(B * S * H) / (4 * 256), 256>>>(E);
    k_decproj<<<B, H>>>(dh, Wd, bd);
    k_score<<<(B * S) / 128, 512, SMEM_SZ>>>(be, Wv, bv, wts);
    k_softmax<<<B, 1024>>>(wts);
    k_ctx_partial<<<dim3(16, B), 128>>>(E, wts);
    k_ctx_reduce<<<(B * H) / 256, 256>>>(ctx);
}

// round 9
// speedup vs baseline: 2.3183x; 1.1788x over previous
#include <cuda_runtime.h>
#include <cuda_fp16.h>
#include <cstdint>

#define B 32
#define S 4096
#define H 512

// ---------------- scratch (no allocs allowed) ----------------
__device__ float g_dec_proj[B * H];
__device__ float g_pctx[16][B * H];
__device__ __align__(16) __half g_Wh[H * H];      // W_enc^T hi fp16, [n][k]
__device__ __align__(16) __half g_Wl[H * H];      // W_enc^T lo fp16
__device__ __align__(16) __half g_Eh[(size_t)B * S * H];  // E fp16 (128 MB)

// ---------------- helpers ----------------
__device__ __forceinline__ uint32_t smem_u32(const void* p) {
    uint32_t a;
    asm("{ .reg .u64 t; cvta.to.shared.u64 t, %1; cvt.u32.u64 %0, t; }" : "=r"(a) : "l"(p));
    return a;
}
// fast tanh: 1 - 2/(exp2(2x/ln2)+1) via MUFU (abs err ~1e-7)
__device__ __forceinline__ float tanh_fast(float x) {
    float e, r;
    asm("ex2.approx.f32 %0, %1;" : "=f"(e) : "f"(x * 2.8853900817779268f));
    asm("rcp.approx.f32 %0, %1;" : "=f"(r) : "f"(e + 1.0f));
    return 1.0f - 2.0f * r;
}
__device__ __forceinline__ void cp16(uint32_t dst, const void* src) {
    asm volatile("cp.async.ca.shared.global [%0], [%1], 16;" :: "r"(dst), "l"(src));
}
__device__ __forceinline__ void ldsm4(uint32_t* r, uint32_t a) {
    asm volatile("ldmatrix.sync.aligned.m8n8.x4.shared.b16 {%0,%1,%2,%3}, [%4];"
                 : "=r"(r[0]), "=r"(r[1]), "=r"(r[2]), "=r"(r[3]) : "r"(a));
}
__device__ __forceinline__ void mma16816(float* d, const uint32_t* a,
                                         uint32_t b0, uint32_t b1) {
    asm volatile(
        "mma.sync.aligned.m16n8k16.row.col.f32.f16.f16.f32 "
        "{%0,%1,%2,%3}, {%4,%5,%6,%7}, {%8,%9}, {%0,%1,%2,%3};"
        : "+f"(d[0]), "+f"(d[1]), "+f"(d[2]), "+f"(d[3])
        : "r"(a[0]), "r"(a[1]), "r"(a[2]), "r"(a[3]), "r"(b0), "r"(b1));
}

// ---------------- SMEM layout for k_score ----------------
// stage (20KB): [Ah 64x64B = 4K][Bh 128x64B = 8K][Bl 8K], 3 stages
#define ST_SZ 20480
#define SDPB  61440
#define SWV   63488
#define SRED  65536
#define SMEM_SZ 66560

#define SWZ(c, r) (((uint32_t)((c) ^ (((r) >> 1) & 3))) << 4)

// ---------------------------------------------------------------------------
// Kernel 0a: split-transpose W_enc -> g_Wh/g_Wl fp16 ([n][k], k-contiguous)
// ---------------------------------------------------------------------------
__global__ void __launch_bounds__(256) k_wconv(const float* __restrict__ W) {
    __shared__ float t[32][33];
    int tx = threadIdx.x & 31, ty = threadIdx.x >> 5;
    int k0 = blockIdx.x * 32, h0 = blockIdx.y * 32;
#pragma unroll
    for (int q = 0; q < 4; ++q)
        t[ty + q * 8][tx] = W[(size_t)(h0 + ty + q * 8) * H + k0 + tx];
    __syncthreads();
#pragma unroll
    for (int q = 0; q < 4; ++q) {
        float v = t[tx][ty + q * 8];
        __half hi = __float2half(v);
        __half lo = __float2half(v - __half2float(hi));
        size_t o = (size_t)(k0 + ty + q * 8) * H + h0 + tx;
        g_Wh[o] = hi;
        g_Wl[o] = lo;
    }
}

// ---------------------------------------------------------------------------
// Kernel 0b: E -> fp16
// ---------------------------------------------------------------------------
__global__ void __launch_bounds__(256) k_esplit(const float* __restrict__ E) {
    size_t i = (size_t)blockIdx.x * 256 + threadIdx.x;
    float4 v = ((const float4*)E)[i];
    __half2 h01 = __floats2half2_rn(v.x, v.y);
    __half2 h23 = __floats2half2_rn(v.z, v.w);
    ((uint2*)g_Eh)[i] = make_uint2(*(uint32_t*)&h01, *(uint32_t*)&h23);
}

// ---------------------------------------------------------------------------
// Kernel 1: dec_proj
// ---------------------------------------------------------------------------
__global__ void __launch_bounds__(H) k_decproj(const float* __restrict__ dh,
                                               const float* __restrict__ Wd,
                                               const float* __restrict__ bd) {
    __shared__ float s_dh[H];
    int b = blockIdx.x, k = threadIdx.x;
    s_dh[k] = dh[b * H + k];
    __syncthreads();
    float acc = bd[k];
#pragma unroll 8
    for (int h = 0; h < H; ++h) acc += s_dh[h] * Wd[h * H + k];
    g_dec_proj[b * H + k] = acc;
}

// ---------------------------------------------------------------------------
// Kernel 2: HMMA fused score. 256 threads, 8 warps (2m x 4n), warp m32 x n32.
// CTA M=64, N in 4 chunks of 128, K in 16 chunks of 32. 3-stage cp.async ring.
// score = tanh(E@We + dpb) @ Wv ; E fp16, We split hi+lo fp16 (2 MMA terms).
// ---------------------------------------------------------------------------
__global__ void __launch_bounds__(256, 3) k_score(
    const float* __restrict__ be, const float* __restrict__ Wvv,
    const float* __restrict__ bv, float* __restrict__ scores) {
    extern __shared__ char smem[];
    uint32_t sb = smem_u32(smem);
    int tid = threadIdx.x;
    int lane = tid & 31, w = tid >> 5;
    int wm = w & 1, wn = w >> 1;
    int m0blk = blockIdx.x * 64;
    int b = m0blk >> 12;

    float* sDPB = (float*)(smem + SDPB);
    float* sWv  = (float*)(smem + SWV);
    float* sRed = (float*)(smem + SRED);   // [4][64]
    for (int i = tid; i < H; i += 256) {
        sDPB[i] = g_dec_proj[b * H + i] + be[i];
        sWv[i]  = Wvv[i];
    }

    // per-thread cp.async source pointers / dest offsets
    int rr = tid >> 2, cc = tid & 3;
    const char* aptr = (const char*)(g_Eh + (size_t)(m0blk + rr) * H + cc * 8);
    const char* bhp  = (const char*)(g_Wh + (size_t)rr * H + cc * 8);
    const char* blp  = (const char*)(g_Wl + (size_t)rr * H + cc * 8);
    uint32_t adst = (uint32_t)(rr * 64) + SWZ(cc, rr);
    uint32_t bdst = 4096u + adst;

    // prologue: stages 0,1
#pragma unroll
    for (int s = 0; s < 2; ++s) {
        uint32_t dbase = sb + s * ST_SZ;
        cp16(dbase + adst, aptr + s * 64);
        cp16(dbase + bdst,         bhp + s * 64);
        cp16(dbase + bdst + 4096,  bhp + 65536 + s * 64);
        cp16(dbase + bdst + 8192,  blp + s * 64);
        cp16(dbase + bdst + 12288, blp + 65536 + s * 64);
        asm volatile("cp.async.commit_group;" ::: "memory");
    }

    // precomputed ldsm offsets
    int mat = lane >> 3, rl = lane & 7;
    uint32_t offA[2][2], offB[2][2];
#pragma unroll
    for (int mi = 0; mi < 2; ++mi) {
        int row = wm * 32 + mi * 16 + (mat & 1) * 8 + rl;
#pragma unroll
        for (int kk = 0; kk < 2; ++kk) {
            int ch = kk * 2 + (mat >> 1);
            offA[mi][kk] = (uint32_t)(row * 64) + SWZ(ch, row);
        }
    }
#pragma unroll
    for (int nt = 0; nt < 2; ++nt) {
        int row = wn * 32 + nt * 16 + (mat & 1) * 8 + rl;
#pragma unroll
        for (int kk = 0; kk < 2; ++kk) {
            int ch = kk * 2 + (mat >> 1);
            offB[nt][kk] = 4096u + (uint32_t)(row * 64) + SWZ(ch, row);
        }
    }

    float acc[2][4][4];
#pragma unroll
    for (int mi = 0; mi < 2; ++mi)
#pragma unroll
        for (int nj = 0; nj < 4; ++nj)
#pragma unroll
            for (int q = 0; q < 4; ++q) acc[mi][nj][q] = 0.f;
    float p[4] = {0.f, 0.f, 0.f, 0.f};

#pragma unroll 1
    for (int s = 0; s < 64; ++s) {
        if (s < 63) { asm volatile("cp.async.wait_group 1;" ::: "memory"); }
        else        { asm volatile("cp.async.wait_group 0;" ::: "memory"); }
        __syncthreads();
        if (s + 2 < 64) {
            int s2 = s + 2;
            int nc2 = s2 >> 4, kc2 = s2 & 15;
            uint32_t dbase = sb + (s2 % 3) * ST_SZ;
            int boff = nc2 * 131072 + kc2 * 64;
            cp16(dbase + adst, aptr + kc2 * 64);
            cp16(dbase + bdst,         bhp + boff);
            cp16(dbase + bdst + 4096,  bhp + 65536 + boff);
            cp16(dbase + bdst + 8192,  blp + boff);
            cp16(dbase + bdst + 12288, blp + 65536 + boff);
            asm volatile("cp.async.commit_group;" ::: "memory");
        }

        int nc = s >> 4, kc = s & 15;
        uint32_t abase = sb + (s % 3) * ST_SZ;

#pragma unroll
        for (int kk = 0; kk < 2; ++kk) {
            uint32_t ah[2][4], bh[2][4], bl[2][4];
#pragma unroll
            for (int mi = 0; mi < 2; ++mi) ldsm4(ah[mi], abase + offA[mi][kk]);
#pragma unroll
            for (int nt = 0; nt < 2; ++nt) {
                ldsm4(bh[nt], abase + offB[nt][kk]);
                ldsm4(bl[nt], abase + 8192 + offB[nt][kk]);
            }
#pragma unroll
            for (int mi = 0; mi < 2; ++mi)
#pragma unroll
                for (int nt = 0; nt < 2; ++nt) {
                    mma16816(acc[mi][nt * 2],     ah[mi], bh[nt][0], bh[nt][2]);
                    mma16816(acc[mi][nt * 2 + 1], ah[mi], bh[nt][1], bh[nt][3]);
                    mma16816(acc[mi][nt * 2],     ah[mi], bl[nt][0], bl[nt][2]);
                    mma16816(acc[mi][nt * 2 + 1], ah[mi], bl[nt][1], bl[nt][3]);
                }
        }

        if (kc == 15) {   // end of N-chunk: fold into score partials
#pragma unroll
            for (int mi = 0; mi < 2; ++mi)
#pragma unroll
                for (int nj = 0; nj < 4; ++nj) {
                    int c0 = nc * 128 + wn * 32 + nj * 8 + (lane & 3) * 2;
                    float d0 = sDPB[c0], d1 = sDPB[c0 + 1];
                    float v0 = sWv[c0],  v1 = sWv[c0 + 1];
                    p[mi * 2]     += tanh_fast(acc[mi][nj][0] + d0) * v0
                                   + tanh_fast(acc[mi][nj][1] + d1) * v1;
                    p[mi * 2 + 1] += tanh_fast(acc[mi][nj][2] + d0) * v0
                                   + tanh_fast(acc[mi][nj][3] + d1) * v1;
#pragma unroll
                    for (int q = 0; q < 4; ++q) acc[mi][nj][q] = 0.f;
                }
        }
    }

    // reduce over lane&3 (4 col groups within warp)
#pragma unroll
    for (int i = 0; i < 4; ++i) {
        p[i] += __shfl_xor_sync(~0u, p[i], 1);
        p[i] += __shfl_xor_sync(~0u, p[i], 2);
    }
    if ((lane & 3) == 0) {
        int g = lane >> 2;
        sRed[wn * 64 + wm * 32 + g]      = p[0];
        sRed[wn * 64 + wm * 32 + 8 + g]  = p[1];
        sRed[wn * 64 + wm * 32 + 16 + g] = p[2];
        sRed[wn * 64 + wm * 32 + 24 + g] = p[3];
    }
    __syncthreads();
    if (tid < 64) {
        float bvv = __ldg(bv);
        scores[m0blk + tid] = sRed[tid] + sRed[64 + tid] + sRed[128 + tid] +
                              sRed[192 + tid] + bvv;
    }
}

// ---------------------------------------------------------------------------
// Kernel 3: in-place softmax over S per batch
// ---------------------------------------------------------------------------
__global__ void __launch_bounds__(1024) k_softmax(float* __restrict__ w) {
    __shared__ float red[32];
    int b = blockIdx.x, tid = threadIdx.x;
    float* p = w + b * S;
    float v[4];
    float m = -1e30f;
#pragma unroll
    for (int i = 0; i < 4; ++i) { v[i] = p[tid + i * 1024]; m = fmaxf(m, v[i]); }
#pragma unroll
    for (int off = 16; off; off >>= 1) m = fmaxf(m, __shfl_xor_sync(~0u, m, off));
    if ((tid & 31) == 0) red[tid >> 5] = m;
    __syncthreads();
    if (tid < 32) {
        float t = red[tid];
#pragma unroll
        for (int off = 16; off; off >>= 1) t = fmaxf(t, __shfl_xor_sync(~0u, t, off));
        if (tid == 0) red[0] = t;
    }
    __syncthreads();
    m = red[0];
    __syncthreads();
    float s = 0.f;
#pragma unroll
    for (int i = 0; i < 4; ++i) { v[i] = expf(v[i] - m); s += v[i]; }
#pragma unroll
    for (int off = 16; off; off >>= 1) s += __shfl_xor_sync(~0u, s, off);
    if ((tid & 31) == 0) red[tid >> 5] = s;
    __syncthreads();
    if (tid < 32) {
        float t = red[tid];
#pragma unroll
        for (int off = 16; off; off >>= 1) t += __shfl_xor_sync(~0u, t, off);
        if (tid == 0) red[0] = t;
    }
    __syncthreads();
    float inv = 1.0f / red[0];
#pragma unroll
    for (int i = 0; i < 4; ++i) p[tid + i * 1024] = v[i] * inv;
}

// ---------------------------------------------------------------------------
// Kernel 4: context partials (float4 columns)
// ---------------------------------------------------------------------------
__global__ void __launch_bounds__(128) k_ctx_partial(const float* __restrict__ E,
                                                     const float* __restrict__ w) {
    int b = blockIdx.y, sc = blockIdx.x;
    const float4* Eb = (const float4*)(E + ((size_t)b * S + (size_t)sc * 256) * H) + threadIdx.x;
    const float* wb = w + b * S + sc * 256;
    float4 acc = make_float4(0.f, 0.f, 0.f, 0.f);
#pragma unroll 4
    for (int s = 0; s < 256; ++s) {
        float ws = __ldg(wb + s);
        float4 e = Eb[(size_t)s * 128];
        acc.x += ws * e.x; acc.y += ws * e.y; acc.z += ws * e.z; acc.w += ws * e.w;
    }
    ((float4*)&g_pctx[sc][b * H])[threadIdx.x] = acc;
}

__global__ void __launch_bounds__(256) k_ctx_reduce(float* __restrict__ ctx) {
    int i = blockIdx.x * 256 + threadIdx.x;
    float a = 0.f;
#pragma unroll
    for (int k = 0; k < 16; ++k) a += g_pctx[k][i];
    ctx[i] = a;
}

// ---------------------------------------------------------------------------
extern "C" void kernel_launch(void* const* d_in, const int* in_sizes, int n_in,
                              void* d_out, int out_size) {
    const float* E  = (const float*)d_in[0];
    const float* dh = (const float*)d_in[1];
    const float* We = (const float*)d_in[2];
    const float* be = (const float*)d_in[3];
    const float* Wd = (const float*)d_in[4];
    const float* bd = (const float*)d_in[5];
    const float* Wv = (const float*)d_in[6];
    const float* bv = (const float*)d_in[7];
    float* out = (float*)d_out;
    float* ctx = out;
    float* wts = out + B * H;

    cudaFuncSetAttribute(k_score, cudaFuncAttributeMaxDynamicSharedMemorySize, SMEM_SZ);

    k_wconv<<<dim3(16, 16), 256>>>(We);
    k_esplit<<<(B * S * H) / (4 * 256), 256>>>(E);
    k_decproj<<<B, H>>>(dh, Wd, bd);
    k_score<<<(B * S) / 64, 256, SMEM_SZ>>>(be, Wv, bv, wts);
    k_softmax<<<B, 1024>>>(wts);
    k_ctx_partial<<<dim3(16, B), 128>>>(E, wts);
    k_ctx_reduce<<<(B * H) / 256, 256>>>(ctx);
}

// round 10
// speedup vs baseline: 3.7576x; 1.6208x over previous
#include <cuda_runtime.h>
#include <cuda_fp16.h>
#include <cstdint>

#define B 32
#define S 4096
#define H 512

// ---------------- scratch (no allocs allowed) ----------------
__device__ float g_dec_proj[B * H];
__device__ float g_pctx[16][B * H];
__device__ __align__(16) __half g_Wh[H * H];              // W_enc^T fp16, [n][k]
__device__ __align__(16) __half g_Eh[(size_t)B * S * H];  // E fp16 (128 MB)

// ---------------- helpers ----------------
__device__ __forceinline__ uint32_t smem_u32(const void* p) {
    uint32_t a;
    asm("{ .reg .u64 t; cvta.to.shared.u64 t, %1; cvt.u32.u64 %0, t; }" : "=r"(a) : "l"(p));
    return a;
}
// fast tanh: 1 - 2/(exp2(2x/ln2)+1) via MUFU (abs err ~1e-7)
__device__ __forceinline__ float tanh_fast(float x) {
    float e, r;
    asm("ex2.approx.f32 %0, %1;" : "=f"(e) : "f"(x * 2.8853900817779268f));
    asm("rcp.approx.f32 %0, %1;" : "=f"(r) : "f"(e + 1.0f));
    return 1.0f - 2.0f * r;
}
__device__ __forceinline__ void cp16(uint32_t dst, const void* src) {
    asm volatile("cp.async.ca.shared.global [%0], [%1], 16;" :: "r"(dst), "l"(src));
}
__device__ __forceinline__ void ldsm4(uint32_t* r, uint32_t a) {
    asm volatile("ldmatrix.sync.aligned.m8n8.x4.shared.b16 {%0,%1,%2,%3}, [%4];"
                 : "=r"(r[0]), "=r"(r[1]), "=r"(r[2]), "=r"(r[3]) : "r"(a));
}
__device__ __forceinline__ void mma16816(float* d, const uint32_t* a,
                                         uint32_t b0, uint32_t b1) {
    asm volatile(
        "mma.sync.aligned.m16n8k16.row.col.f32.f16.f16.f32 "
        "{%0,%1,%2,%3}, {%4,%5,%6,%7}, {%8,%9}, {%0,%1,%2,%3};"
        : "+f"(d[0]), "+f"(d[1]), "+f"(d[2]), "+f"(d[3])
        : "r"(a[0]), "r"(a[1]), "r"(a[2]), "r"(a[3]), "r"(b0), "r"(b1));
}

// ---------------- SMEM layout for k_score ----------------
// stage (12KB): [A 64x64B = 4K][Bh 128x64B = 8K], 3 stages
#define ST_SZ 12288
#define SDPB  36864
#define SWV   38912
#define SRED  40960
#define SMEM_SZ 41984

#define SWZ(c, r) (((uint32_t)((c) ^ (((r) >> 1) & 3))) << 4)

// ---------------------------------------------------------------------------
// Kernel 0a: transpose W_enc -> g_Wh fp16 ([n][k], k-contiguous)
// ---------------------------------------------------------------------------
__global__ void __launch_bounds__(256) k_wconv(const float* __restrict__ W) {
    __shared__ float t[32][33];
    int tx = threadIdx.x & 31, ty = threadIdx.x >> 5;
    int k0 = blockIdx.x * 32, h0 = blockIdx.y * 32;
#pragma unroll
    for (int q = 0; q < 4; ++q)
        t[ty + q * 8][tx] = W[(size_t)(h0 + ty + q * 8) * H + k0 + tx];
    __syncthreads();
#pragma unroll
    for (int q = 0; q < 4; ++q) {
        float v = t[tx][ty + q * 8];
        g_Wh[(size_t)(k0 + ty + q * 8) * H + h0 + tx] = __float2half(v);
    }
}

// ---------------------------------------------------------------------------
// Kernel 0b: E -> fp16
// ---------------------------------------------------------------------------
__global__ void __launch_bounds__(256) k_esplit(const float* __restrict__ E) {
    size_t i = (size_t)blockIdx.x * 256 + threadIdx.x;
    float4 v = ((const float4*)E)[i];
    __half2 h01 = __floats2half2_rn(v.x, v.y);
    __half2 h23 = __floats2half2_rn(v.z, v.w);
    ((uint2*)g_Eh)[i] = make_uint2(*(uint32_t*)&h01, *(uint32_t*)&h23);
}

// ---------------------------------------------------------------------------
// Kernel 1: dec_proj
// ---------------------------------------------------------------------------
__global__ void __launch_bounds__(H) k_decproj(const float* __restrict__ dh,
                                               const float* __restrict__ Wd,
                                               const float* __restrict__ bd) {
    __shared__ float s_dh[H];
    int b = blockIdx.x, k = threadIdx.x;
    s_dh[k] = dh[b * H + k];
    __syncthreads();
    float acc = bd[k];
#pragma unroll 8
    for (int h = 0; h < H; ++h) acc += s_dh[h] * Wd[h * H + k];
    g_dec_proj[b * H + k] = acc;
}

// ---------------------------------------------------------------------------
// Kernel 2: HMMA fused score. 256 threads, 8 warps (2m x 4n), warp m32 x n32.
// CTA M=64, N in 4 chunks of 128, K in 16 chunks of 32. 3-stage cp.async ring.
// score = tanh(E@We + dpb) @ Wv ; E fp16, We fp16 (single MMA term).
// ---------------------------------------------------------------------------
__global__ void __launch_bounds__(256, 3) k_score(
    const float* __restrict__ be, const float* __restrict__ Wvv,
    const float* __restrict__ bv, float* __restrict__ scores) {
    extern __shared__ char smem[];
    uint32_t sb = smem_u32(smem);
    int tid = threadIdx.x;
    int lane = tid & 31, w = tid >> 5;
    int wm = w & 1, wn = w >> 1;
    int m0blk = blockIdx.x * 64;
    int b = m0blk >> 12;

    float* sDPB = (float*)(smem + SDPB);
    float* sWv  = (float*)(smem + SWV);
    float* sRed = (float*)(smem + SRED);   // [4][64]
    for (int i = tid; i < H; i += 256) {
        sDPB[i] = g_dec_proj[b * H + i] + be[i];
        sWv[i]  = Wvv[i];
    }

    // per-thread cp.async source pointers / dest offsets
    int rr = tid >> 2, cc = tid & 3;
    const char* aptr = (const char*)(g_Eh + (size_t)(m0blk + rr) * H + cc * 8);
    const char* bhp  = (const char*)(g_Wh + (size_t)rr * H + cc * 8);
    uint32_t adst = (uint32_t)(rr * 64) + SWZ(cc, rr);
    uint32_t bdst = 4096u + adst;

    // prologue: stages 0,1
#pragma unroll
    for (int s = 0; s < 2; ++s) {
        uint32_t dbase = sb + s * ST_SZ;
        cp16(dbase + adst, aptr + s * 64);
        cp16(dbase + bdst,        bhp + s * 64);
        cp16(dbase + bdst + 4096, bhp + 65536 + s * 64);
        asm volatile("cp.async.commit_group;" ::: "memory");
    }

    // precomputed ldsm offsets
    int mat = lane >> 3, rl = lane & 7;
    uint32_t offA[2][2], offB[2][2];
#pragma unroll
    for (int mi = 0; mi < 2; ++mi) {
        int row = wm * 32 + mi * 16 + (mat & 1) * 8 + rl;
#pragma unroll
        for (int kk = 0; kk < 2; ++kk) {
            int ch = kk * 2 + (mat >> 1);
            offA[mi][kk] = (uint32_t)(row * 64) + SWZ(ch, row);
        }
    }
#pragma unroll
    for (int nt = 0; nt < 2; ++nt) {
        int row = wn * 32 + nt * 16 + (mat & 1) * 8 + rl;
#pragma unroll
        for (int kk = 0; kk < 2; ++kk) {
            int ch = kk * 2 + (mat >> 1);
            offB[nt][kk] = 4096u + (uint32_t)(row * 64) + SWZ(ch, row);
        }
    }

    float acc[2][4][4];
#pragma unroll
    for (int mi = 0; mi < 2; ++mi)
#pragma unroll
        for (int nj = 0; nj < 4; ++nj)
#pragma unroll
            for (int q = 0; q < 4; ++q) acc[mi][nj][q] = 0.f;
    float p[4] = {0.f, 0.f, 0.f, 0.f};

#pragma unroll 1
    for (int s = 0; s < 64; ++s) {
        if (s < 63) { asm volatile("cp.async.wait_group 1;" ::: "memory"); }
        else        { asm volatile("cp.async.wait_group 0;" ::: "memory"); }
        __syncthreads();
        if (s + 2 < 64) {
            int s2 = s + 2;
            int nc2 = s2 >> 4, kc2 = s2 & 15;
            uint32_t dbase = sb + (s2 % 3) * ST_SZ;
            int boff = nc2 * 131072 + kc2 * 64;
            cp16(dbase + adst, aptr + kc2 * 64);
            cp16(dbase + bdst,        bhp + boff);
            cp16(dbase + bdst + 4096, bhp + 65536 + boff);
            asm volatile("cp.async.commit_group;" ::: "memory");
        }

        int nc = s >> 4, kc = s & 15;
        uint32_t abase = sb + (s % 3) * ST_SZ;

#pragma unroll
        for (int kk = 0; kk < 2; ++kk) {
            uint32_t ah[2][4], bh[2][4];
#pragma unroll
            for (int mi = 0; mi < 2; ++mi) ldsm4(ah[mi], abase + offA[mi][kk]);
#pragma unroll
            for (int nt = 0; nt < 2; ++nt) ldsm4(bh[nt], abase + offB[nt][kk]);
#pragma unroll
            for (int mi = 0; mi < 2; ++mi)
#pragma unroll
                for (int nt = 0; nt < 2; ++nt) {
                    mma16816(acc[mi][nt * 2],     ah[mi], bh[nt][0], bh[nt][2]);
                    mma16816(acc[mi][nt * 2 + 1], ah[mi], bh[nt][1], bh[nt][3]);
                }
        }

        if (kc == 15) {   // end of N-chunk: fold into score partials
#pragma unroll
            for (int mi = 0; mi < 2; ++mi)
#pragma unroll
                for (int nj = 0; nj < 4; ++nj) {
                    int c0 = nc * 128 + wn * 32 + nj * 8 + (lane & 3) * 2;
                    float d0 = sDPB[c0], d1 = sDPB[c0 + 1];
                    float v0 = sWv[c0],  v1 = sWv[c0 + 1];
                    p[mi * 2]     += tanh_fast(acc[mi][nj][0] + d0) * v0
                                   + tanh_fast(acc[mi][nj][1] + d1) * v1;
                    p[mi * 2 + 1] += tanh_fast(acc[mi][nj][2] + d0) * v0
                                   + tanh_fast(acc[mi][nj][3] + d1) * v1;
#pragma unroll
                    for (int q = 0; q < 4; ++q) acc[mi][nj][q] = 0.f;
                }
        }
    }

    // reduce over lane&3 (4 col groups within warp)
#pragma unroll
    for (int i = 0; i < 4; ++i) {
        p[i] += __shfl_xor_sync(~0u, p[i], 1);
        p[i] += __shfl_xor_sync(~0u, p[i], 2);
    }
    if ((lane & 3) == 0) {
        int g = lane >> 2;
        sRed[wn * 64 + wm * 32 + g]      = p[0];
        sRed[wn * 64 + wm * 32 + 8 + g]  = p[1];
        sRed[wn * 64 + wm * 32 + 16 + g] = p[2];
        sRed[wn * 64 + wm * 32 + 24 + g] = p[3];
    }
    __syncthreads();
    if (tid < 64) {
        float bvv = __ldg(bv);
        scores[m0blk + tid] = sRed[tid] + sRed[64 + tid] + sRed[128 + tid] +
                              sRed[192 + tid] + bvv;
    }
}

// ---------------------------------------------------------------------------
// Kernel 3: in-place softmax over S per batch
// ---------------------------------------------------------------------------
__global__ void __launch_bounds__(1024) k_softmax(float* __restrict__ w) {
    __shared__ float red[32];
    int b = blockIdx.x, tid = threadIdx.x;
    float* p = w + b * S;
    float v[4];
    float m = -1e30f;
#pragma unroll
    for (int i = 0; i < 4; ++i) { v[i] = p[tid + i * 1024]; m = fmaxf(m, v[i]); }
#pragma unroll
    for (int off = 16; off; off >>= 1) m = fmaxf(m, __shfl_xor_sync(~0u, m, off));
    if ((tid & 31) == 0) red[tid >> 5] = m;
    __syncthreads();
    if (tid < 32) {
        float t = red[tid];
#pragma unroll
        for (int off = 16; off; off >>= 1) t = fmaxf(t, __shfl_xor_sync(~0u, t, off));
        if (tid == 0) red[0] = t;
    }
    __syncthreads();
    m = red[0];
    __syncthreads();
    float s = 0.f;
#pragma unroll
    for (int i = 0; i < 4; ++i) { v[i] = expf(v[i] - m); s += v[i]; }
#pragma unroll
    for (int off = 16; off; off >>= 1) s += __shfl_xor_sync(~0u, s, off);
    if ((tid & 31) == 0) red[tid >> 5] = s;
    __syncthreads();
    if (tid < 32) {
        float t = red[tid];
#pragma unroll
        for (int off = 16; off; off >>= 1) t += __shfl_xor_sync(~0u, t, off);
        if (tid == 0) red[0] = t;
    }
    __syncthreads();
    float inv = 1.0f / red[0];
#pragma unroll
    for (int i = 0; i < 4; ++i) p[tid + i * 1024] = v[i] * inv;
}

// ---------------------------------------------------------------------------
// Kernel 4: context partials from fp16 E (half the DRAM traffic)
// grid (sc=16, b=32), block 64: thread t owns cols [8t, 8t+7]
// ---------------------------------------------------------------------------
__global__ void __launch_bounds__(64) k_ctx_partial(const float* __restrict__ w) {
    int b = blockIdx.y, sc = blockIdx.x;
    const uint4* Eb = (const uint4*)(g_Eh + ((size_t)b * S + (size_t)sc * 256) * H)
                      + threadIdx.x;
    const float* wb = w + b * S + sc * 256;
    float acc[8];
#pragma unroll
    for (int j = 0; j < 8; ++j) acc[j] = 0.f;
#pragma unroll 4
    for (int s = 0; s < 256; ++s) {
        float ws = __ldg(wb + s);
        uint4 e = Eb[(size_t)s * 64];
        float2 f0 = __half22float2(*(__half2*)&e.x);
        float2 f1 = __half22float2(*(__half2*)&e.y);
        float2 f2 = __half22float2(*(__half2*)&e.z);
        float2 f3 = __half22float2(*(__half2*)&e.w);
        acc[0] += ws * f0.x; acc[1] += ws * f0.y;
        acc[2] += ws * f1.x; acc[3] += ws * f1.y;
        acc[4] += ws * f2.x; acc[5] += ws * f2.y;
        acc[6] += ws * f3.x; acc[7] += ws * f3.y;
    }
    float* dst = &g_pctx[sc][b * H] + threadIdx.x * 8;
    *(float4*)dst       = make_float4(acc[0], acc[1], acc[2], acc[3]);
    *(float4*)(dst + 4) = make_float4(acc[4], acc[5], acc[6], acc[7]);
}

__global__ void __launch_bounds__(256) k_ctx_reduce(float* __restrict__ ctx) {
    int i = blockIdx.x * 256 + threadIdx.x;
    float a = 0.f;
#pragma unroll
    for (int k = 0; k < 16; ++k) a += g_pctx[k][i];
    ctx[i] = a;
}

// ---------------------------------------------------------------------------
extern "C" void kernel_launch(void* const* d_in, const int* in_sizes, int n_in,
                              void* d_out, int out_size) {
    const float* E  = (const float*)d_in[0];
    const float* dh = (const float*)d_in[1];
    const float* We = (const float*)d_in[2];
    const float* be = (const float*)d_in[3];
    const float* Wd = (const float*)d_in[4];
    const float* bd = (const float*)d_in[5];
    const float* Wv = (const float*)d_in[6];
    const float* bv = (const float*)d_in[7];
    float* out = (float*)d_out;
    float* ctx = out;
    float* wts = out + B * H;

    cudaFuncSetAttribute(k_score, cudaFuncAttributeMaxDynamicSharedMemorySize, SMEM_SZ);

    k_wconv<<<dim3(16, 16), 256>>>(We);
    k_esplit<<<(B * S * H) / (4 * 256), 256>>>(E);
    k_decproj<<<B, H>>>(dh, Wd, bd);
    k_score<<<(B * S) / 64, 256, SMEM_SZ>>>(be, Wv, bv, wts);
    k_softmax<<<B, 1024>>>(wts);
    k_ctx_partial<<<dim3(16, B), 64>>>(wts);
    k_ctx_reduce<<<(B * H) / 256, 256>>>(ctx);
}

// round 11
// speedup vs baseline: 3.9565x; 1.0529x over previous
#include <cuda_runtime.h>
#include <cuda_fp16.h>
#include <cstdint>

#define B 32
#define S 4096
#define H 512

// ---------------- scratch (no allocs allowed) ----------------
__device__ float g_dec_proj[B * H];
__device__ float g_pctx[16][B * H];
__device__ __align__(16) __half g_Wh[H * H];              // W_enc^T fp16, [n][k]
__device__ __align__(16) __half g_Eh[(size_t)B * S * H];  // E fp16 (128 MB)

// ---------------- helpers ----------------
__device__ __forceinline__ uint32_t smem_u32(const void* p) {
    uint32_t a;
    asm("{ .reg .u64 t; cvta.to.shared.u64 t, %1; cvt.u32.u64 %0, t; }" : "=r"(a) : "l"(p));
    return a;
}
// fast tanh: 1 - 2/(exp2(2x/ln2)+1) via MUFU (abs err ~1e-7)
__device__ __forceinline__ float tanh_fast(float x) {
    float e, r;
    asm("ex2.approx.f32 %0, %1;" : "=f"(e) : "f"(x * 2.8853900817779268f));
    asm("rcp.approx.f32 %0, %1;" : "=f"(r) : "f"(e + 1.0f));
    return 1.0f - 2.0f * r;
}
__device__ __forceinline__ void cp16(uint32_t dst, const void* src) {
    asm volatile("cp.async.ca.shared.global [%0], [%1], 16;" :: "r"(dst), "l"(src));
}
__device__ __forceinline__ void ldsm4(uint32_t* r, uint32_t a) {
    asm volatile("ldmatrix.sync.aligned.m8n8.x4.shared.b16 {%0,%1,%2,%3}, [%4];"
                 : "=r"(r[0]), "=r"(r[1]), "=r"(r[2]), "=r"(r[3]) : "r"(a));
}
__device__ __forceinline__ void mma16816(float* d, const uint32_t* a,
                                         uint32_t b0, uint32_t b1) {
    asm volatile(
        "mma.sync.aligned.m16n8k16.row.col.f32.f16.f16.f32 "
        "{%0,%1,%2,%3}, {%4,%5,%6,%7}, {%8,%9}, {%0,%1,%2,%3};"
        : "+f"(d[0]), "+f"(d[1]), "+f"(d[2]), "+f"(d[3])
        : "r"(a[0]), "r"(a[1]), "r"(a[2]), "r"(a[3]), "r"(b0), "r"(b1));
}

// ---------------- SMEM layout for k_score ----------------
// stage (20KB): [A 64x64B = 4K][B 256x64B = 16K], 3 stages
#define ST_SZ 20480
#define SDPB  61440
#define SWV   63488
#define SRED  65536
#define SMEM_SZ 66560

#define SWZ(c, r) (((uint32_t)((c) ^ (((r) >> 1) & 3))) << 4)

// ---------------------------------------------------------------------------
// Kernel 0a: transpose W_enc -> g_Wh fp16 ([n][k], k-contiguous)
// ---------------------------------------------------------------------------
__global__ void __launch_bounds__(256) k_wconv(const float* __restrict__ W) {
    __shared__ float t[32][33];
    int tx = threadIdx.x & 31, ty = threadIdx.x >> 5;
    int k0 = blockIdx.x * 32, h0 = blockIdx.y * 32;
#pragma unroll
    for (int q = 0; q < 4; ++q)
        t[ty + q * 8][tx] = W[(size_t)(h0 + ty + q * 8) * H + k0 + tx];
    __syncthreads();
#pragma unroll
    for (int q = 0; q < 4; ++q) {
        float v = t[tx][ty + q * 8];
        g_Wh[(size_t)(k0 + ty + q * 8) * H + h0 + tx] = __float2half(v);
    }
}

// ---------------------------------------------------------------------------
// Kernel 0b: E -> fp16
// ---------------------------------------------------------------------------
__global__ void __launch_bounds__(256) k_esplit(const float* __restrict__ E) {
    size_t i = (size_t)blockIdx.x * 256 + threadIdx.x;
    float4 v = ((const float4*)E)[i];
    __half2 h01 = __floats2half2_rn(v.x, v.y);
    __half2 h23 = __floats2half2_rn(v.z, v.w);
    ((uint2*)g_Eh)[i] = make_uint2(*(uint32_t*)&h01, *(uint32_t*)&h23);
}

// ---------------------------------------------------------------------------
// Kernel 1: dec_proj
// ---------------------------------------------------------------------------
__global__ void __launch_bounds__(H) k_decproj(const float* __restrict__ dh,
                                               const float* __restrict__ Wd,
                                               const float* __restrict__ bd) {
    __shared__ float s_dh[H];
    int b = blockIdx.x, k = threadIdx.x;
    s_dh[k] = dh[b * H + k];
    __syncthreads();
    float acc = bd[k];
#pragma unroll 8
    for (int h = 0; h < H; ++h) acc += s_dh[h] * Wd[h * H + k];
    g_dec_proj[b * H + k] = acc;
}

// ---------------------------------------------------------------------------
// Kernel 2: HMMA fused score. 256 threads, 8 warps (2m x 4n), warp m32 x n64.
// CTA M=64, N in 2 chunks of 256, K in 16 chunks of 32. 3-stage cp.async ring.
// ---------------------------------------------------------------------------
__global__ void __launch_bounds__(256, 2) k_score(
    const float* __restrict__ be, const float* __restrict__ Wvv,
    const float* __restrict__ bv, float* __restrict__ scores) {
    extern __shared__ char smem[];
    uint32_t sb = smem_u32(smem);
    int tid = threadIdx.x;
    int lane = tid & 31, w = tid >> 5;
    int wm = w & 1, wn = w >> 1;
    int m0blk = blockIdx.x * 64;
    int b = m0blk >> 12;

    float* sDPB = (float*)(smem + SDPB);
    float* sWv  = (float*)(smem + SWV);
    float* sRed = (float*)(smem + SRED);   // [4][64]
    for (int i = tid; i < H; i += 256) {
        sDPB[i] = g_dec_proj[b * H + i] + be[i];
        sWv[i]  = Wvv[i];
    }

    // per-thread cp.async source pointers / dest offsets
    int rr = tid >> 2, cc = tid & 3;
    const char* aptr = (const char*)(g_Eh + (size_t)(m0blk + rr) * H + cc * 8);
    const char* bhp  = (const char*)(g_Wh + (size_t)rr * H + cc * 8);
    uint32_t adst = (uint32_t)(rr * 64) + SWZ(cc, rr);
    uint32_t bdst = 4096u + adst;

    // prologue: stages 0,1 (nc=0, kc=s)
#pragma unroll
    for (int s = 0; s < 2; ++s) {
        uint32_t dbase = sb + s * ST_SZ;
        cp16(dbase + adst, aptr + s * 64);
        cp16(dbase + bdst,         bhp + s * 64);
        cp16(dbase + bdst + 4096,  bhp + s * 64 + 65536);
        cp16(dbase + bdst + 8192,  bhp + s * 64 + 131072);
        cp16(dbase + bdst + 12288, bhp + s * 64 + 196608);
        asm volatile("cp.async.commit_group;" ::: "memory");
    }

    // ldsm offsets for kk=0; kk=1 = offset ^ 32 (swizzle bit-5 flip)
    int mat = lane >> 3, rl = lane & 7;
    uint32_t offA[2], offB[4];
    {
        int ch = mat >> 1;
#pragma unroll
        for (int mi = 0; mi < 2; ++mi) {
            int row = wm * 32 + mi * 16 + (mat & 1) * 8 + rl;
            offA[mi] = (uint32_t)(row * 64) + SWZ(ch, row);
        }
#pragma unroll
        for (int nt = 0; nt < 4; ++nt) {
            int row = wn * 64 + nt * 16 + (mat & 1) * 8 + rl;
            offB[nt] = 4096u + (uint32_t)(row * 64) + SWZ(ch, row);
        }
    }

    float acc[2][8][4];
#pragma unroll
    for (int mi = 0; mi < 2; ++mi)
#pragma unroll
        for (int nj = 0; nj < 8; ++nj)
#pragma unroll
            for (int q = 0; q < 4; ++q) acc[mi][nj][q] = 0.f;
    float p[4] = {0.f, 0.f, 0.f, 0.f};

#pragma unroll 1
    for (int s = 0; s < 32; ++s) {
        if (s < 31) { asm volatile("cp.async.wait_group 1;" ::: "memory"); }
        else        { asm volatile("cp.async.wait_group 0;" ::: "memory"); }
        __syncthreads();
        if (s + 2 < 32) {
            int s2 = s + 2;
            int nc2 = s2 >> 4, kc2 = s2 & 15;
            uint32_t dbase = sb + (s2 % 3) * ST_SZ;
            int boff = nc2 * 262144 + kc2 * 64;
            cp16(dbase + adst, aptr + kc2 * 64);
            cp16(dbase + bdst,         bhp + boff);
            cp16(dbase + bdst + 4096,  bhp + boff + 65536);
            cp16(dbase + bdst + 8192,  bhp + boff + 131072);
            cp16(dbase + bdst + 12288, bhp + boff + 196608);
            asm volatile("cp.async.commit_group;" ::: "memory");
        }

        int nc = s >> 4, kc = s & 15;
        uint32_t abase = sb + (s % 3) * ST_SZ;

#pragma unroll
        for (int kk = 0; kk < 2; ++kk) {
            uint32_t xr = kk ? 32u : 0u;
            uint32_t ah[2][4], bh[4][4];
#pragma unroll
            for (int mi = 0; mi < 2; ++mi) ldsm4(ah[mi], abase + (offA[mi] ^ xr));
#pragma unroll
            for (int nt = 0; nt < 4; ++nt) ldsm4(bh[nt], abase + (offB[nt] ^ xr));
#pragma unroll
            for (int mi = 0; mi < 2; ++mi)
#pragma unroll
                for (int nt = 0; nt < 4; ++nt) {
                    mma16816(acc[mi][nt * 2],     ah[mi], bh[nt][0], bh[nt][2]);
                    mma16816(acc[mi][nt * 2 + 1], ah[mi], bh[nt][1], bh[nt][3]);
                }
        }

        if (kc == 15) {   // end of N-chunk: fold into score partials
#pragma unroll
            for (int mi = 0; mi < 2; ++mi)
#pragma unroll
                for (int nj = 0; nj < 8; ++nj) {
                    int c0 = nc * 256 + wn * 64 + nj * 8 + (lane & 3) * 2;
                    float d0 = sDPB[c0], d1 = sDPB[c0 + 1];
                    float v0 = sWv[c0],  v1 = sWv[c0 + 1];
                    p[mi * 2]     += tanh_fast(acc[mi][nj][0] + d0) * v0
                                   + tanh_fast(acc[mi][nj][1] + d1) * v1;
                    p[mi * 2 + 1] += tanh_fast(acc[mi][nj][2] + d0) * v0
                                   + tanh_fast(acc[mi][nj][3] + d1) * v1;
#pragma unroll
                    for (int q = 0; q < 4; ++q) acc[mi][nj][q] = 0.f;
                }
        }
    }

    // reduce over lane&3 (4 col groups within warp)
#pragma unroll
    for (int i = 0; i < 4; ++i) {
        p[i] += __shfl_xor_sync(~0u, p[i], 1);
        p[i] += __shfl_xor_sync(~0u, p[i], 2);
    }
    if ((lane & 3) == 0) {
        int g = lane >> 2;
        sRed[wn * 64 + wm * 32 + g]      = p[0];   // mi=0 rows
        sRed[wn * 64 + wm * 32 + 8 + g]  = p[1];
        sRed[wn * 64 + wm * 32 + 16 + g] = p[2];   // mi=1 rows
        sRed[wn * 64 + wm * 32 + 24 + g] = p[3];
    }
    __syncthreads();
    if (tid < 64) {
        float bvv = __ldg(bv);
        scores[m0blk + tid] = sRed[tid] + sRed[64 + tid] + sRed[128 + tid] +
                              sRed[192 + tid] + bvv;
    }
}

// ---------------------------------------------------------------------------
// Kernel 3: in-place softmax over S per batch
// ---------------------------------------------------------------------------
__global__ void __launch_bounds__(1024) k_softmax(float* __restrict__ w) {
    __shared__ float red[32];
    int b = blockIdx.x, tid = threadIdx.x;
    float* p = w + b * S;
    float v[4];
    float m = -1e30f;
#pragma unroll
    for (int i = 0; i < 4; ++i) { v[i] = p[tid + i * 1024]; m = fmaxf(m, v[i]); }
#pragma unroll
    for (int off = 16; off; off >>= 1) m = fmaxf(m, __shfl_xor_sync(~0u, m, off));
    if ((tid & 31) == 0) red[tid >> 5] = m;
    __syncthreads();
    if (tid < 32) {
        float t = red[tid];
#pragma unroll
        for (int off = 16; off; off >>= 1) t = fmaxf(t, __shfl_xor_sync(~0u, t, off));
        if (tid == 0) red[0] = t;
    }
    __syncthreads();
    m = red[0];
    __syncthreads();
    float s = 0.f;
#pragma unroll
    for (int i = 0; i < 4; ++i) { v[i] = expf(v[i] - m); s += v[i]; }
#pragma unroll
    for (int off = 16; off; off >>= 1) s += __shfl_xor_sync(~0u, s, off);
    if ((tid & 31) == 0) red[tid >> 5] = s;
    __syncthreads();
    if (tid < 32) {
        float t = red[tid];
#pragma unroll
        for (int off = 16; off; off >>= 1) t += __shfl_xor_sync(~0u, t, off);
        if (tid == 0) red[0] = t;
    }
    __syncthreads();
    float inv = 1.0f / red[0];
#pragma unroll
    for (int i = 0; i < 4; ++i) p[tid + i * 1024] = v[i] * inv;
}

// ---------------------------------------------------------------------------
// Kernel 4: context partials from fp16 E (half the DRAM traffic)
// ---------------------------------------------------------------------------
__global__ void __launch_bounds__(64) k_ctx_partial(const float* __restrict__ w) {
    int b = blockIdx.y, sc = blockIdx.x;
    const uint4* Eb = (const uint4*)(g_Eh + ((size_t)b * S + (size_t)sc * 256) * H)
                      + threadIdx.x;
    const float* wb = w + b * S + sc * 256;
    float acc[8];
#pragma unroll
    for (int j = 0; j < 8; ++j) acc[j] = 0.f;
#pragma unroll 4
    for (int s = 0; s < 256; ++s) {
        float ws = __ldg(wb + s);
        uint4 e = Eb[(size_t)s * 64];
        float2 f0 = __half22float2(*(__half2*)&e.x);
        float2 f1 = __half22float2(*(__half2*)&e.y);
        float2 f2 = __half22float2(*(__half2*)&e.z);
        float2 f3 = __half22float2(*(__half2*)&e.w);
        acc[0] += ws * f0.x; acc[1] += ws * f0.y;
        acc[2] += ws * f1.x; acc[3] += ws * f1.y;
        acc[4] += ws * f2.x; acc[5] += ws * f2.y;
        acc[6] += ws * f3.x; acc[7] += ws * f3.y;
    }
    float* dst = &g_pctx[sc][b * H] + threadIdx.x * 8;
    *(float4*)dst       = make_float4(acc[0], acc[1], acc[2], acc[3]);
    *(float4*)(dst + 4) = make_float4(acc[4], acc[5], acc[6], acc[7]);
}

__global__ void __launch_bounds__(256) k_ctx_reduce(float* __restrict__ ctx) {
    int i = blockIdx.x * 256 + threadIdx.x;
    float a = 0.f;
#pragma unroll
    for (int k = 0; k < 16; ++k) a += g_pctx[k][i];
    ctx[i] = a;
}

// ---------------------------------------------------------------------------
extern "C" void kernel_launch(void* const* d_in, const int* in_sizes, int n_in,
                              void* d_out, int out_size) {
    const float* E  = (const float*)d_in[0];
    const float* dh = (const float*)d_in[1];
    const float* We = (const float*)d_in[2];
    const float* be = (const float*)d_in[3];
    const float* Wd = (const float*)d_in[4];
    const float* bd = (const float*)d_in[5];
    const float* Wv = (const float*)d_in[6];
    const float* bv = (const float*)d_in[7];
    float* out = (float*)d_out;
    float* ctx = out;
    float* wts = out + B * H;

    cudaFuncSetAttribute(k_score, cudaFuncAttributeMaxDynamicSharedMemorySize, SMEM_SZ);

    k_wconv<<<dim3(16, 16), 256>>>(We);
    k_esplit<<<(B * S * H) / (4 * 256), 256>>>(E);
    k_decproj<<<B, H>>>(dh, Wd, bd);
    k_score<<<(B * S) / 64, 256, SMEM_SZ>>>(be, Wv, bv, wts);
    k_softmax<<<B, 1024>>>(wts);
    k_ctx_partial<<<dim3(16, B), 64>>>(wts);
    k_ctx_reduce<<<(B * H) / 256, 256>>>(ctx);
}

// round 15
// speedup vs baseline: 3.9696x; 1.0033x over previous
#include <cuda_runtime.h>
#include <cuda_fp16.h>
#include <cstdint>

#define B 32
#define S 4096
#define H 512

// ---------------- scratch (no allocs allowed) ----------------
__device__ float g_dec_proj[B * H];
__device__ float g_pctx[16][B * H];
__device__ __align__(16) __half g_Wh[H * H];              // W_enc^T fp16, [n][k]
__device__ __align__(16) __half g_Eh[(size_t)B * S * H];  // E fp16 (128 MB)

// ---------------- helpers ----------------
__device__ __forceinline__ uint32_t smem_u32(const void* p) {
    uint32_t a;
    asm("{ .reg .u64 t; cvta.to.shared.u64 t, %1; cvt.u32.u64 %0, t; }" : "=r"(a) : "l"(p));
    return a;
}
// fast tanh: 1 - 2/(exp2(2x/ln2)+1) via MUFU (abs err ~1e-7)
__device__ __forceinline__ float tanh_fast(float x) {
    float e, r;
    asm("ex2.approx.f32 %0, %1;" : "=f"(e) : "f"(x * 2.8853900817779268f));
    asm("rcp.approx.f32 %0, %1;" : "=f"(r) : "f"(e + 1.0f));
    return 1.0f - 2.0f * r;
}
__device__ __forceinline__ void cp16(uint32_t dst, const void* src) {
    asm volatile("cp.async.ca.shared.global [%0], [%1], 16;" :: "r"(dst), "l"(src));
}
__device__ __forceinline__ void ldsm4(uint32_t* r, uint32_t a) {
    asm volatile("ldmatrix.sync.aligned.m8n8.x4.shared.b16 {%0,%1,%2,%3}, [%4];"
                 : "=r"(r[0]), "=r"(r[1]), "=r"(r[2]), "=r"(r[3]) : "r"(a));
}
__device__ __forceinline__ void mma16816(float* d, const uint32_t* a,
                                         uint32_t b0, uint32_t b1) {
    asm volatile(
        "mma.sync.aligned.m16n8k16.row.col.f32.f16.f16.f32 "
        "{%0,%1,%2,%3}, {%4,%5,%6,%7}, {%8,%9}, {%0,%1,%2,%3};"
        : "+f"(d[0]), "+f"(d[1]), "+f"(d[2]), "+f"(d[3])
        : "r"(a[0]), "r"(a[1]), "r"(a[2]), "r"(a[3]), "r"(b0), "r"(b1));
}

// ---------------- SMEM layout for k_score ----------------
// stage (48KB): [A 128 rows x 128B = 16K][B 256 rows x 128B = 32K], 3 stages
#define ST_SZ 49152
#define SDPB  147456
#define SWV   149504
#define SRED  151552
#define SMEM_SZ 153600

// ---------------------------------------------------------------------------
// Kernel 0a: transpose W_enc -> g_Wh fp16 ([n][k], k-contiguous)
// ---------------------------------------------------------------------------
__global__ void __launch_bounds__(256) k_wconv(const float* __restrict__ W) {
    __shared__ float t[32][33];
    int tx = threadIdx.x & 31, ty = threadIdx.x >> 5;
    int k0 = blockIdx.x * 32, h0 = blockIdx.y * 32;
#pragma unroll
    for (int q = 0; q < 4; ++q)
        t[ty + q * 8][tx] = W[(size_t)(h0 + ty + q * 8) * H + k0 + tx];
    __syncthreads();
#pragma unroll
    for (int q = 0; q < 4; ++q) {
        float v = t[tx][ty + q * 8];
        g_Wh[(size_t)(k0 + ty + q * 8) * H + h0 + tx] = __float2half(v);
    }
}

// ---------------------------------------------------------------------------
// Kernel 0b: E -> fp16
// ---------------------------------------------------------------------------
__global__ void __launch_bounds__(256) k_esplit(const float* __restrict__ E) {
    size_t i = (size_t)blockIdx.x * 256 + threadIdx.x;
    float4 v = ((const float4*)E)[i];
    __half2 h01 = __floats2half2_rn(v.x, v.y);
    __half2 h23 = __floats2half2_rn(v.z, v.w);
    ((uint2*)g_Eh)[i] = make_uint2(*(uint32_t*)&h01, *(uint32_t*)&h23);
}

// ---------------------------------------------------------------------------
// Kernel 1: dec_proj
// ---------------------------------------------------------------------------
__global__ void __launch_bounds__(H) k_decproj(const float* __restrict__ dh,
                                               const float* __restrict__ Wd,
                                               const float* __restrict__ bd) {
    __shared__ float s_dh[H];
    int b = blockIdx.x, k = threadIdx.x;
    s_dh[k] = dh[b * H + k];
    __syncthreads();
    float acc = bd[k];
#pragma unroll 8
    for (int h = 0; h < H; ++h) acc += s_dh[h] * Wd[h * H + k];
    g_dec_proj[b * H + k] = acc;
}

// ---------------------------------------------------------------------------
// Kernel 2: HMMA fused score. 512 threads, 16 warps (4m x 4n), warp m32 x n64.
// CTA M=128, N in 2 chunks of 256, K in 8 chunks of 64. 3-stage cp.async ring.
// ---------------------------------------------------------------------------
__global__ void __launch_bounds__(512, 1) k_score(
    const float* __restrict__ be, const float* __restrict__ Wvv,
    const float* __restrict__ bv, float* __restrict__ scores) {
    extern __shared__ char smem[];
    uint32_t sb = smem_u32(smem);
    int tid = threadIdx.x;
    int lane = tid & 31, w = tid >> 5;
    int wm = w & 3, wn = w >> 2;
    int m0blk = blockIdx.x * 128;
    int b = m0blk >> 12;

    float* sDPB = (float*)(smem + SDPB);
    float* sWv  = (float*)(smem + SWV);
    float* sRed = (float*)(smem + SRED);   // [4][128]
    sDPB[tid] = g_dec_proj[b * H + tid] + be[tid];
    sWv[tid]  = Wvv[tid];

    // ---- per-thread cp.async src pointers / swizzled dst offsets ----
    // A: 128 rows x 8 chunks; thread: row=tid>>2, chunks c=(tid&3)+{0,4}
    int ar = tid >> 2, ac = tid & 3;
    const char* aptr = (const char*)(g_Eh + (size_t)(m0blk + ar) * H) + ac * 16;
    uint32_t adst0 = (uint32_t)(ar * 128) + (((uint32_t)(ac       ^ (ar & 7))) << 4);
    uint32_t adst1 = (uint32_t)(ar * 128) + (((uint32_t)((ac + 4) ^ (ar & 7))) << 4);
    // B: 256 rows x 8 chunks; thread: row=tid>>1, chunks c=(tid&1)*4+{0..3}
    int br = tid >> 1, bc0 = (tid & 1) * 4;
    const char* bptr = (const char*)(g_Wh + (size_t)br * H) + bc0 * 16;
    uint32_t bdst[4];
#pragma unroll
    for (int q = 0; q < 4; ++q)
        bdst[q] = 16384u + (uint32_t)(br * 128) + (((uint32_t)((bc0 + q) ^ (br & 7))) << 4);

    // prologue: steps 0,1  (nc = 0, kc = s)
#pragma unroll
    for (int s = 0; s < 2; ++s) {
        uint32_t dbase = sb + s * ST_SZ;
        const char* asrc = aptr + s * 128;
        cp16(dbase + adst0, asrc);
        cp16(dbase + adst1, asrc + 64);
        const char* bsrc = bptr + s * 128;
#pragma unroll
        for (int q = 0; q < 4; ++q) cp16(dbase + bdst[q], bsrc + q * 16);
        asm volatile("cp.async.commit_group;" ::: "memory");
    }

    // ---- ldsm offsets (kk=0); kk advances via XOR (kk<<5) ----
    int mat = lane >> 3, rl = lane & 7;
    int ch0 = mat >> 1;
    uint32_t offA[2], offB[4];
#pragma unroll
    for (int mi = 0; mi < 2; ++mi) {
        int row = wm * 32 + mi * 16 + (mat & 1) * 8 + rl;
        offA[mi] = (uint32_t)(row * 128) + (((uint32_t)(ch0 ^ (row & 7))) << 4);
    }
#pragma unroll
    for (int nt = 0; nt < 4; ++nt) {
        int row = wn * 64 + nt * 16 + (mat & 1) * 8 + rl;
        offB[nt] = 16384u + (uint32_t)(row * 128) + (((uint32_t)(ch0 ^ (row & 7))) << 4);
    }

    float acc[2][8][4];
#pragma unroll
    for (int mi = 0; mi < 2; ++mi)
#pragma unroll
        for (int nj = 0; nj < 8; ++nj)
#pragma unroll
            for (int q = 0; q < 4; ++q) acc[mi][nj][q] = 0.f;
    float p[4] = {0.f, 0.f, 0.f, 0.f};

#pragma unroll 1
    for (int s = 0; s < 16; ++s) {
        if (s < 15) { asm volatile("cp.async.wait_group 1;" ::: "memory"); }
        else        { asm volatile("cp.async.wait_group 0;" ::: "memory"); }
        __syncthreads();
        if (s + 2 < 16) {
            int s2 = s + 2;
            int nc2 = s2 >> 3, kc2 = s2 & 7;
            uint32_t dbase = sb + (s2 % 3) * ST_SZ;
            const char* asrc = aptr + kc2 * 128;
            cp16(dbase + adst0, asrc);
            cp16(dbase + adst1, asrc + 64);
            // N-chunk stride: 256 rows x 1024 B/row = 262144 bytes
            const char* bsrc = bptr + nc2 * 262144 + kc2 * 128;
#pragma unroll
            for (int q = 0; q < 4; ++q) cp16(dbase + bdst[q], bsrc + q * 16);
            asm volatile("cp.async.commit_group;" ::: "memory");
        }

        int nc = s >> 3, kc = s & 7;
        uint32_t abase = sb + (s % 3) * ST_SZ;

#pragma unroll
        for (int kk = 0; kk < 4; ++kk) {
            uint32_t xr = ((uint32_t)kk) << 5;
            uint32_t ah[2][4], bh[4][4];
#pragma unroll
            for (int mi = 0; mi < 2; ++mi) ldsm4(ah[mi], abase + (offA[mi] ^ xr));
#pragma unroll
            for (int nt = 0; nt < 4; ++nt) ldsm4(bh[nt], abase + (offB[nt] ^ xr));
#pragma unroll
            for (int mi = 0; mi < 2; ++mi)
#pragma unroll
                for (int nt = 0; nt < 4; ++nt) {
                    mma16816(acc[mi][nt * 2],     ah[mi], bh[nt][0], bh[nt][2]);
                    mma16816(acc[mi][nt * 2 + 1], ah[mi], bh[nt][1], bh[nt][3]);
                }
        }

        if (kc == 7) {   // end of N-chunk: fold into score partials
#pragma unroll
            for (int mi = 0; mi < 2; ++mi)
#pragma unroll
                for (int nj = 0; nj < 8; ++nj) {
                    int c0 = nc * 256 + wn * 64 + nj * 8 + (lane & 3) * 2;
                    float d0 = sDPB[c0], d1 = sDPB[c0 + 1];
                    float v0 = sWv[c0],  v1 = sWv[c0 + 1];
                    p[mi * 2]     += tanh_fast(acc[mi][nj][0] + d0) * v0
                                   + tanh_fast(acc[mi][nj][1] + d1) * v1;
                    p[mi * 2 + 1] += tanh_fast(acc[mi][nj][2] + d0) * v0
                                   + tanh_fast(acc[mi][nj][3] + d1) * v1;
#pragma unroll
                    for (int q = 0; q < 4; ++q) acc[mi][nj][q] = 0.f;
                }
        }
    }

    // reduce over lane&3 (4 col groups within warp)
#pragma unroll
    for (int i = 0; i < 4; ++i) {
        p[i] += __shfl_xor_sync(~0u, p[i], 1);
        p[i] += __shfl_xor_sync(~0u, p[i], 2);
    }
    if ((lane & 3) == 0) {
        int g = lane >> 2;
        sRed[wn * 128 + wm * 32 + g]      = p[0];   // mi=0 rows
        sRed[wn * 128 + wm * 32 + 8 + g]  = p[1];
        sRed[wn * 128 + wm * 32 + 16 + g] = p[2];   // mi=1 rows
        sRed[wn * 128 + wm * 32 + 24 + g] = p[3];
    }
    __syncthreads();
    if (tid < 128) {
        float bvv = __ldg(bv);
        scores[m0blk + tid] = sRed[tid] + sRed[128 + tid] + sRed[256 + tid] +
                              sRed[384 + tid] + bvv;
    }
}

// ---------------------------------------------------------------------------
// Kernel 3: in-place softmax over S per batch
// ---------------------------------------------------------------------------
__global__ void __launch_bounds__(1024) k_softmax(float* __restrict__ w) {
    __shared__ float red[32];
    int b = blockIdx.x, tid = threadIdx.x;
    float* p = w + b * S;
    float v[4];
    float m = -1e30f;
#pragma unroll
    for (int i = 0; i < 4; ++i) { v[i] = p[tid + i * 1024]; m = fmaxf(m, v[i]); }
#pragma unroll
    for (int off = 16; off; off >>= 1) m = fmaxf(m, __shfl_xor_sync(~0u, m, off));
    if ((tid & 31) == 0) red[tid >> 5] = m;
    __syncthreads();
    if (tid < 32) {
        float t = red[tid];
#pragma unroll
        for (int off = 16; off; off >>= 1) t = fmaxf(t, __shfl_xor_sync(~0u, t, off));
        if (tid == 0) red[0] = t;
    }
    __syncthreads();
    m = red[0];
    __syncthreads();
    float s = 0.f;
#pragma unroll
    for (int i = 0; i < 4; ++i) { v[i] = expf(v[i] - m); s += v[i]; }
#pragma unroll
    for (int off = 16; off; off >>= 1) s += __shfl_xor_sync(~0u, s, off);
    if ((tid & 31) == 0) red[tid >> 5] = s;
    __syncthreads();
    if (tid < 32) {
        float t = red[tid];
#pragma unroll
        for (int off = 16; off; off >>= 1) t += __shfl_xor_sync(~0u, t, off);
        if (tid == 0) red[0] = t;
    }
    __syncthreads();
    float inv = 1.0f / red[0];
#pragma unroll
    for (int i = 0; i < 4; ++i) p[tid + i * 1024] = v[i] * inv;
}

// ---------------------------------------------------------------------------
// Kernel 4: context partials from fp16 E (half the DRAM traffic)
// ---------------------------------------------------------------------------
__global__ void __launch_bounds__(64) k_ctx_partial(const float* __restrict__ w) {
    int b = blockIdx.y, sc = blockIdx.x;
    const uint4* Eb = (const uint4*)(g_Eh + ((size_t)b * S + (size_t)sc * 256) * H)
                      + threadIdx.x;
    const float* wb = w + b * S + sc * 256;
    float acc[8];
#pragma unroll
    for (int j = 0; j < 8; ++j) acc[j] = 0.f;
#pragma unroll 4
    for (int s = 0; s < 256; ++s) {
        float ws = __ldg(wb + s);
        uint4 e = Eb[(size_t)s * 64];
        float2 f0 = __half22float2(*(__half2*)&e.x);
        float2 f1 = __half22float2(*(__half2*)&e.y);
        float2 f2 = __half22float2(*(__half2*)&e.z);
        float2 f3 = __half22float2(*(__half2*)&e.w);
        acc[0] += ws * f0.x; acc[1] += ws * f0.y;
        acc[2] += ws * f1.x; acc[3] += ws * f1.y;
        acc[4] += ws * f2.x; acc[5] += ws * f2.y;
        acc[6] += ws * f3.x; acc[7] += ws * f3.y;
    }
    float* dst = &g_pctx[sc][b * H] + threadIdx.x * 8;
    *(float4*)dst       = make_float4(acc[0], acc[1], acc[2], acc[3]);
    *(float4*)(dst + 4) = make_float4(acc[4], acc[5], acc[6], acc[7]);
}

__global__ void __launch_bounds__(256) k_ctx_reduce(float* __restrict__ ctx) {
    int i = blockIdx.x * 256 + threadIdx.x;
    float a = 0.f;
#pragma unroll
    for (int k = 0; k < 16; ++k) a += g_pctx[k][i];
    ctx[i] = a;
}

// ---------------------------------------------------------------------------
extern "C" void kernel_launch(void* const* d_in, const int* in_sizes, int n_in,
                              void* d_out, int out_size) {
    const float* E  = (const float*)d_in[0];
    const float* dh = (const float*)d_in[1];
    const float* We = (const float*)d_in[2];
    const float* be = (const float*)d_in[3];
    const float* Wd = (const float*)d_in[4];
    const float* bd = (const float*)d_in[5];
    const float* Wv = (const float*)d_in[6];
    const float* bv = (const float*)d_in[7];
    float* out = (float*)d_out;
    float* ctx = out;
    float* wts = out + B * H;

    cudaFuncSetAttribute(k_score, cudaFuncAttributeMaxDynamicSharedMemorySize, SMEM_SZ);

    k_wconv<<<dim3(16, 16), 256>>>(We);
    k_esplit<<<(B * S * H) / (4 * 256), 256>>>(E);
    k_decproj<<<B, H>>>(dh, Wd, bd);
    k_score<<<(B * S) / 128, 512, SMEM_SZ>>>(be, Wv, bv, wts);
    k_softmax<<<B, 1024>>>(wts);
    k_ctx_partial<<<dim3(16, B), 64>>>(wts);
    k_ctx_reduce<<<(B * H) / 256, 256>>>(ctx);
}

// round 16
// speedup vs baseline: 4.2626x; 1.0738x over previous
#include <cuda_runtime.h>
#include <cuda_fp16.h>
#include <cstdint>

#define B 32
#define S 4096
#define H 512

// ---------------- scratch (no allocs allowed) ----------------
__device__ float g_dec_proj[B * H];
__device__ float g_pctx[16][B * H];
__device__ __align__(16) __half g_Wh[H * H];   // W_enc^T fp16, [n][k]

// ---------------- helpers ----------------
__device__ __forceinline__ uint32_t smem_u32(const void* p) {
    uint32_t a;
    asm("{ .reg .u64 t; cvta.to.shared.u64 t, %1; cvt.u32.u64 %0, t; }" : "=r"(a) : "l"(p));
    return a;
}
// fast tanh: 1 - 2/(exp2(2x/ln2)+1) via MUFU (abs err ~1e-7)
__device__ __forceinline__ float tanh_fast(float x) {
    float e, r;
    asm("ex2.approx.f32 %0, %1;" : "=f"(e) : "f"(x * 2.8853900817779268f));
    asm("rcp.approx.f32 %0, %1;" : "=f"(r) : "f"(e + 1.0f));
    return 1.0f - 2.0f * r;
}
__device__ __forceinline__ void cp16(uint32_t dst, const void* src) {
    asm volatile("cp.async.ca.shared.global [%0], [%1], 16;" :: "r"(dst), "l"(src));
}
__device__ __forceinline__ void ldsm4(uint32_t* r, uint32_t a) {
    asm volatile("ldmatrix.sync.aligned.m8n8.x4.shared.b16 {%0,%1,%2,%3}, [%4];"
                 : "=r"(r[0]), "=r"(r[1]), "=r"(r[2]), "=r"(r[3]) : "r"(a));
}
__device__ __forceinline__ void mma16816(float* d, const uint32_t* a,
                                         uint32_t b0, uint32_t b1) {
    asm volatile(
        "mma.sync.aligned.m16n8k16.row.col.f32.f16.f16.f32 "
        "{%0,%1,%2,%3}, {%4,%5,%6,%7}, {%8,%9}, {%0,%1,%2,%3};"
        : "+f"(d[0]), "+f"(d[1]), "+f"(d[2]), "+f"(d[3])
        : "r"(a[0]), "r"(a[1]), "r"(a[2]), "r"(a[3]), "r"(b0), "r"(b1));
}
__device__ __forceinline__ uint4 cvt8(float4 a, float4 b) {
    __half2 h0 = __floats2half2_rn(a.x, a.y);
    __half2 h1 = __floats2half2_rn(a.z, a.w);
    __half2 h2 = __floats2half2_rn(b.x, b.y);
    __half2 h3 = __floats2half2_rn(b.z, b.w);
    return make_uint4(*(uint32_t*)&h0, *(uint32_t*)&h1,
                      *(uint32_t*)&h2, *(uint32_t*)&h3);
}

// ---------------- SMEM layout for k_score ----------------
// stage (48KB): [A 128 rows x 128B = 16K][B 256 rows x 128B = 32K], 3 stages
#define ST_SZ 49152
#define SDPB  147456
#define SWV   149504
#define SRED  151552
#define SMEM_SZ 153600

// ---------------------------------------------------------------------------
// Kernel 0: transpose W_enc -> g_Wh fp16 ([n][k], k-contiguous)
// ---------------------------------------------------------------------------
__global__ void __launch_bounds__(256) k_wconv(const float* __restrict__ W) {
    __shared__ float t[32][33];
    int tx = threadIdx.x & 31, ty = threadIdx.x >> 5;
    int k0 = blockIdx.x * 32, h0 = blockIdx.y * 32;
#pragma unroll
    for (int q = 0; q < 4; ++q)
        t[ty + q * 8][tx] = W[(size_t)(h0 + ty + q * 8) * H + k0 + tx];
    __syncthreads();
#pragma unroll
    for (int q = 0; q < 4; ++q) {
        float v = t[tx][ty + q * 8];
        g_Wh[(size_t)(k0 + ty + q * 8) * H + h0 + tx] = __float2half(v);
    }
}

// ---------------------------------------------------------------------------
// Kernel 1: dec_proj
// ---------------------------------------------------------------------------
__global__ void __launch_bounds__(H) k_decproj(const float* __restrict__ dh,
                                               const float* __restrict__ Wd,
                                               const float* __restrict__ bd) {
    __shared__ float s_dh[H];
    int b = blockIdx.x, k = threadIdx.x;
    s_dh[k] = dh[b * H + k];
    __syncthreads();
    float acc = bd[k];
#pragma unroll 8
    for (int h = 0; h < H; ++h) acc += s_dh[h] * Wd[h * H + k];
    g_dec_proj[b * H + k] = acc;
}

// ---------------------------------------------------------------------------
// Kernel 2: HMMA fused score. 512 threads, 16 warps (4m x 4n), warp m32 x n64.
// CTA M=128, N in 2 chunks of 256, K in 8 chunks of 64. 3-stage ring.
// A: LDG fp32 E -> cvt fp16 -> STS (fused esplit). B: cp.async of g_Wh.
// ---------------------------------------------------------------------------
__global__ void __launch_bounds__(512, 1) k_score(
    const float* __restrict__ E, const float* __restrict__ be,
    const float* __restrict__ Wvv, const float* __restrict__ bv,
    float* __restrict__ scores) {
    extern __shared__ char smem[];
    uint32_t sb = smem_u32(smem);
    int tid = threadIdx.x;
    int lane = tid & 31, w = tid >> 5;
    int wm = w & 3, wn = w >> 2;
    int m0blk = blockIdx.x * 128;
    int b = m0blk >> 12;

    float* sDPB = (float*)(smem + SDPB);
    float* sWv  = (float*)(smem + SWV);
    float* sRed = (float*)(smem + SRED);   // [4][128]
    sDPB[tid] = g_dec_proj[b * H + tid] + be[tid];
    sWv[tid]  = Wvv[tid];

    // ---- A path: fp32 LDG + cvt + STS.  thread: row=tid>>2, chunks ac, ac+4 ----
    int ar = tid >> 2, ac = tid & 3;
    const float* aptr = E + (size_t)(m0blk + ar) * H;   // fp32 row
    uint32_t adst0 = (uint32_t)(ar * 128) + (((uint32_t)(ac       ^ (ar & 7))) << 4);
    uint32_t adst1 = (uint32_t)(ar * 128) + (((uint32_t)((ac + 4) ^ (ar & 7))) << 4);
    // ---- B path: cp.async; thread: row=tid>>1, chunks bc0..bc0+3 ----
    int br = tid >> 1, bc0 = (tid & 1) * 4;
    const char* bptr = (const char*)(g_Wh + (size_t)br * H) + bc0 * 16;
    uint32_t bdst[4];
#pragma unroll
    for (int q = 0; q < 4; ++q)
        bdst[q] = 16384u + (uint32_t)(br * 128) + (((uint32_t)((bc0 + q) ^ (br & 7))) << 4);

    // prologue: stages 0,1  (nc = 0, kc = s)
#pragma unroll
    for (int s = 0; s < 2; ++s) {
        uint32_t dbase = sb + s * ST_SZ;
        const char* bsrc = bptr + s * 128;
#pragma unroll
        for (int q = 0; q < 4; ++q) cp16(dbase + bdst[q], bsrc + q * 16);
        asm volatile("cp.async.commit_group;" ::: "memory");
        const float* asrc = aptr + s * 64;
        float4 x0 = *(const float4*)(asrc + ac * 8);
        float4 x1 = *(const float4*)(asrc + ac * 8 + 4);
        float4 y0 = *(const float4*)(asrc + (ac + 4) * 8);
        float4 y1 = *(const float4*)(asrc + (ac + 4) * 8 + 4);
        *(uint4*)(smem + s * ST_SZ + adst0) = cvt8(x0, x1);
        *(uint4*)(smem + s * ST_SZ + adst1) = cvt8(y0, y1);
    }

    // ---- ldsm offsets (kk=0); kk advances via XOR (kk<<5) ----
    int mat = lane >> 3, rl = lane & 7;
    int ch0 = mat >> 1;
    uint32_t offA[2], offB[4];
#pragma unroll
    for (int mi = 0; mi < 2; ++mi) {
        int row = wm * 32 + mi * 16 + (mat & 1) * 8 + rl;
        offA[mi] = (uint32_t)(row * 128) + (((uint32_t)(ch0 ^ (row & 7))) << 4);
    }
#pragma unroll
    for (int nt = 0; nt < 4; ++nt) {
        int row = wn * 64 + nt * 16 + (mat & 1) * 8 + rl;
        offB[nt] = 16384u + (uint32_t)(row * 128) + (((uint32_t)(ch0 ^ (row & 7))) << 4);
    }

    float acc[2][8][4];
#pragma unroll
    for (int mi = 0; mi < 2; ++mi)
#pragma unroll
        for (int nj = 0; nj < 8; ++nj)
#pragma unroll
            for (int q = 0; q < 4; ++q) acc[mi][nj][q] = 0.f;
    float p[4] = {0.f, 0.f, 0.f, 0.f};

#pragma unroll 1
    for (int s = 0; s < 16; ++s) {
        if (s < 15) { asm volatile("cp.async.wait_group 1;" ::: "memory"); }
        else        { asm volatile("cp.async.wait_group 0;" ::: "memory"); }
        __syncthreads();

        float4 x0, x1, y0, y1;
        int s2 = s + 2;
        bool pf = (s2 < 16);
        uint32_t pbase = (uint32_t)((s2 % 3) * ST_SZ);
        if (pf) {
            int nc2 = s2 >> 3, kc2 = s2 & 7;
            // B prefetch (N-chunk stride: 256 rows x 1024 B/row = 262144 B)
            const char* bsrc = bptr + nc2 * 262144 + kc2 * 128;
#pragma unroll
            for (int q = 0; q < 4; ++q) cp16(sb + pbase + bdst[q], bsrc + q * 16);
            asm volatile("cp.async.commit_group;" ::: "memory");
            // A fp32 LDG (converted + STS'd after the MMA block)
            const float* asrc = aptr + kc2 * 64;
            x0 = *(const float4*)(asrc + ac * 8);
            x1 = *(const float4*)(asrc + ac * 8 + 4);
            y0 = *(const float4*)(asrc + (ac + 4) * 8);
            y1 = *(const float4*)(asrc + (ac + 4) * 8 + 4);
        }

        int nc = s >> 3, kc = s & 7;
        uint32_t abase = sb + (s % 3) * ST_SZ;

#pragma unroll
        for (int kk = 0; kk < 4; ++kk) {
            uint32_t xr = ((uint32_t)kk) << 5;
            uint32_t ah[2][4], bh[4][4];
#pragma unroll
            for (int mi = 0; mi < 2; ++mi) ldsm4(ah[mi], abase + (offA[mi] ^ xr));
#pragma unroll
            for (int nt = 0; nt < 4; ++nt) ldsm4(bh[nt], abase + (offB[nt] ^ xr));
#pragma unroll
            for (int mi = 0; mi < 2; ++mi)
#pragma unroll
                for (int nt = 0; nt < 4; ++nt) {
                    mma16816(acc[mi][nt * 2],     ah[mi], bh[nt][0], bh[nt][2]);
                    mma16816(acc[mi][nt * 2 + 1], ah[mi], bh[nt][1], bh[nt][3]);
                }
        }

        if (pf) {   // A cvt + STS into stage (s+2)%3 (visible after next sync)
            *(uint4*)(smem + pbase + adst0) = cvt8(x0, x1);
            *(uint4*)(smem + pbase + adst1) = cvt8(y0, y1);
        }

        if (kc == 7) {   // end of N-chunk: fold into score partials
#pragma unroll
            for (int mi = 0; mi < 2; ++mi)
#pragma unroll
                for (int nj = 0; nj < 8; ++nj) {
                    int c0 = nc * 256 + wn * 64 + nj * 8 + (lane & 3) * 2;
                    float d0 = sDPB[c0], d1 = sDPB[c0 + 1];
                    float v0 = sWv[c0],  v1 = sWv[c0 + 1];
                    p[mi * 2]     += tanh_fast(acc[mi][nj][0] + d0) * v0
                                   + tanh_fast(acc[mi][nj][1] + d1) * v1;
                    p[mi * 2 + 1] += tanh_fast(acc[mi][nj][2] + d0) * v0
                                   + tanh_fast(acc[mi][nj][3] + d1) * v1;
#pragma unroll
                    for (int q = 0; q < 4; ++q) acc[mi][nj][q] = 0.f;
                }
        }
    }

    // reduce over lane&3 (4 col groups within warp)
#pragma unroll
    for (int i = 0; i < 4; ++i) {
        p[i] += __shfl_xor_sync(~0u, p[i], 1);
        p[i] += __shfl_xor_sync(~0u, p[i], 2);
    }
    if ((lane & 3) == 0) {
        int g = lane >> 2;
        sRed[wn * 128 + wm * 32 + g]      = p[0];   // mi=0 rows
        sRed[wn * 128 + wm * 32 + 8 + g]  = p[1];
        sRed[wn * 128 + wm * 32 + 16 + g] = p[2];   // mi=1 rows
        sRed[wn * 128 + wm * 32 + 24 + g] = p[3];
    }
    __syncthreads();
    if (tid < 128) {
        float bvv = __ldg(bv);
        scores[m0blk + tid] = sRed[tid] + sRed[128 + tid] + sRed[256 + tid] +
                              sRed[384 + tid] + bvv;
    }
}

// ---------------------------------------------------------------------------
// Kernel 3: in-place softmax over S per batch
// ---------------------------------------------------------------------------
__global__ void __launch_bounds__(1024) k_softmax(float* __restrict__ w) {
    __shared__ float red[32];
    int b = blockIdx.x, tid = threadIdx.x;
    float* p = w + b * S;
    float v[4];
    float m = -1e30f;
#pragma unroll
    for (int i = 0; i < 4; ++i) { v[i] = p[tid + i * 1024]; m = fmaxf(m, v[i]); }
#pragma unroll
    for (int off = 16; off; off >>= 1) m = fmaxf(m, __shfl_xor_sync(~0u, m, off));
    if ((tid & 31) == 0) red[tid >> 5] = m;
    __syncthreads();
    if (tid < 32) {
        float t = red[tid];
#pragma unroll
        for (int off = 16; off; off >>= 1) t = fmaxf(t, __shfl_xor_sync(~0u, t, off));
        if (tid == 0) red[0] = t;
    }
    __syncthreads();
    m = red[0];
    __syncthreads();
    float s = 0.f;
#pragma unroll
    for (int i = 0; i < 4; ++i) { v[i] = expf(v[i] - m); s += v[i]; }
#pragma unroll
    for (int off = 16; off; off >>= 1) s += __shfl_xor_sync(~0u, s, off);
    if ((tid & 31) == 0) red[tid >> 5] = s;
    __syncthreads();
    if (tid < 32) {
        float t = red[tid];
#pragma unroll
        for (int off = 16; off; off >>= 1) t += __shfl_xor_sync(~0u, t, off);
        if (tid == 0) red[0] = t;
    }
    __syncthreads();
    float inv = 1.0f / red[0];
#pragma unroll
    for (int i = 0; i < 4; ++i) p[tid + i * 1024] = v[i] * inv;
}

// ---------------------------------------------------------------------------
// Kernel 4: context partials (fp32 E, float4 columns)
// ---------------------------------------------------------------------------
__global__ void __launch_bounds__(128) k_ctx_partial(const float* __restrict__ E,
                                                     const float* __restrict__ w) {
    int b = blockIdx.y, sc = blockIdx.x;
    const float4* Eb = (const float4*)(E + ((size_t)b * S + (size_t)sc * 256) * H) + threadIdx.x;
    const float* wb = w + b * S + sc * 256;
    float4 acc = make_float4(0.f, 0.f, 0.f, 0.f);
#pragma unroll 4
    for (int s = 0; s < 256; ++s) {
        float ws = __ldg(wb + s);
        float4 e = Eb[(size_t)s * 128];
        acc.x += ws * e.x; acc.y += ws * e.y; acc.z += ws * e.z; acc.w += ws * e.w;
    }
    ((float4*)&g_pctx[sc][b * H])[threadIdx.x] = acc;
}

__global__ void __launch_bounds__(256) k_ctx_reduce(float* __restrict__ ctx) {
    int i = blockIdx.x * 256 + threadIdx.x;
    float a = 0.f;
#pragma unroll
    for (int k = 0; k < 16; ++k) a += g_pctx[k][i];
    ctx[i] = a;
}

// ---------------------------------------------------------------------------
extern "C" void kernel_launch(void* const* d_in, const int* in_sizes, int n_in,
                              void* d_out, int out_size) {
    const float* E  = (const float*)d_in[0];
    const float* dh = (const float*)d_in[1];
    const float* We = (const float*)d_in[2];
    const float* be = (const float*)d_in[3];
    const float* Wd = (const float*)d_in[4];
    const float* bd = (const float*)d_in[5];
    const float* Wv = (const float*)d_in[6];
    const float* bv = (const float*)d_in[7];
    float* out = (float*)d_out;
    float* ctx = out;
    float* wts = out + B * H;

    cudaFuncSetAttribute(k_score, cudaFuncAttributeMaxDynamicSharedMemorySize, SMEM_SZ);

    k_wconv<<<dim3(16, 16), 256>>>(We);
    k_decproj<<<B, H>>>(dh, Wd, bd);
    k_score<<<(B * S) / 128, 512, SMEM_SZ>>>(E, be, Wv, bv, wts);
    k_softmax<<<B, 1024>>>(wts);
    k_ctx_partial<<<dim3(16, B), 128>>>(E, wts);
    k_ctx_reduce<<<(B * H) / 256, 256>>>(ctx);
}